// round 14
// baseline (speedup 1.0000x reference)
#include <cuda_runtime.h>
#include <cuda_bf16.h>
#include <cstdint>
#include <math.h>

#define BB 16
#define DDIM 512
#define FFF 2048
#define NLAYERS 6
#define MROWS (BB*512)

typedef __nv_bfloat16 bf16;
typedef __nv_bfloat162 bf162;

// ---------------- scratch ----------------
__device__ __align__(256) float g_t [MROWS*DDIM];
__device__ __align__(256) bf16 g_xh [MROWS*DDIM];
__device__ __align__(256) bf16 g_xl [MROWS*DDIM];
__device__ __align__(256) bf16 g_qkvh[MROWS*1536];
__device__ __align__(256) bf16 g_qkvl[MROWS*1536];
__device__ __align__(256) bf16 g_kvh [MROWS*1024];
__device__ __align__(256) bf16 g_kvl [MROWS*1024];
__device__ __align__(256) bf16 g_aoh[MROWS*DDIM];
__device__ __align__(256) bf16 g_aol[MROWS*DDIM];
__device__ __align__(256) bf16 g_memh[MROWS*DDIM];
__device__ __align__(256) bf16 g_meml[MROWS*DDIM];
__device__ __align__(256) bf16 g_ffh[MROWS*FFF];
__device__ __align__(256) bf16 g_ffl[MROWS*FFF];
__device__ __align__(256) bf16 g_inh[MROWS*128];
__device__ __align__(256) bf16 g_inl[MROWS*128];
__device__ __align__(256) bf16 g_wh_attn[48*512*512];
__device__ __align__(256) bf16 g_wl_attn[48*512*512];
__device__ __align__(256) bf16 g_wh_ff1 [6*2048*512];
__device__ __align__(256) bf16 g_wl_ff1 [6*2048*512];
__device__ __align__(256) bf16 g_wh_ff2 [6*512*2048];
__device__ __align__(256) bf16 g_wl_ff2 [6*512*2048];
__device__ __align__(256) bf16 g_wh_exp [512*128];
__device__ __align__(256) bf16 g_wl_exp [512*128];

// ---------------- helpers ----------------
__device__ __forceinline__ uint32_t smem_u32(const void* p){
    uint32_t a; asm("{ .reg .u64 t; cvta.to.shared.u64 t, %1; cvt.u32.u64 %0, t; }":"=r"(a):"l"(p)); return a;
}
__device__ __forceinline__ void ldm_x4(uint32_t* r, uint32_t addr){
    asm volatile("ldmatrix.sync.aligned.m8n8.x4.shared.b16 {%0,%1,%2,%3}, [%4];"
        : "=r"(r[0]),"=r"(r[1]),"=r"(r[2]),"=r"(r[3]) : "r"(addr));
}
__device__ __forceinline__ void ldm_x4t(uint32_t* r, uint32_t addr){
    asm volatile("ldmatrix.sync.aligned.m8n8.x4.trans.shared.b16 {%0,%1,%2,%3}, [%4];"
        : "=r"(r[0]),"=r"(r[1]),"=r"(r[2]),"=r"(r[3]) : "r"(addr));
}
__device__ __forceinline__ void cpa16(uint32_t dst, const void* src){
    asm volatile("cp.async.cg.shared.global [%0], [%1], 16;" :: "r"(dst), "l"(src));
}
__device__ __forceinline__ void mma_bf16(float* d, const uint32_t* a, uint32_t b0, uint32_t b1){
    asm volatile(
        "mma.sync.aligned.m16n8k16.row.col.f32.bf16.bf16.f32 "
        "{%0,%1,%2,%3}, {%4,%5,%6,%7}, {%8,%9}, {%0,%1,%2,%3};"
        : "+f"(d[0]), "+f"(d[1]), "+f"(d[2]), "+f"(d[3])
        : "r"(a[0]), "r"(a[1]), "r"(a[2]), "r"(a[3]), "r"(b0), "r"(b1));
}
__device__ __forceinline__ uint32_t pack2(bf16 a, bf16 b){ bf162 h; h.x=a; h.y=b; return *(uint32_t*)&h; }
__device__ __forceinline__ bf16 bfh(float v){ return __float2bfloat16_rn(v); }
__device__ __forceinline__ float bff(bf16 v){ return __bfloat162float(v); }

// ---------------- transpose + split weights ----------------
__global__ void tsplit_kernel(const float* __restrict__ W, bf16* __restrict__ Hi,
                              bf16* __restrict__ Lo, int K, int N)
{
    __shared__ float t[32][33];
    const float* Wm = W + (size_t)blockIdx.z*K*N;
    bf16* Hm = Hi + (size_t)blockIdx.z*K*N;
    bf16* Lm = Lo + (size_t)blockIdx.z*K*N;
    int n0=blockIdx.x*32, k0=blockIdx.y*32, x=threadIdx.x, y=threadIdx.y;
#pragma unroll
    for (int i=0;i<32;i+=8) t[y+i][x] = Wm[(size_t)(k0+y+i)*N + n0+x];
    __syncthreads();
#pragma unroll
    for (int i=0;i<32;i+=8){
        float v = t[x][y+i];
        bf16 h = bfh(v);
        Hm[(size_t)(n0+y+i)*K + k0+x] = h;
        Lm[(size_t)(n0+y+i)*K + k0+x] = bfh(v - bff(h));
    }
}
__global__ void csplit_kernel(const float* __restrict__ X, bf16* __restrict__ H,
                              bf16* __restrict__ L, int n)
{
    int i = blockIdx.x*blockDim.x + threadIdx.x;
    if (i < n){
        float v = X[i];
        bf16 h = bfh(v);
        H[i] = h; L[i] = bfh(v - bff(h));
    }
}

// ---------------- GEMM (R10 proven core; bf16 hi/lo residual) ----------------
#define BM 128
#define BN 128
#define BK 32
#define SROW 80
#define OPSZ (128*SROW)
#define STG (4*OPSZ)
#define GEMM_SMEM (2*STG)

__global__ __launch_bounds__(256, 2)
void tc_gemm(const bf16* __restrict__ AHg, const bf16* __restrict__ ALg,
             const bf16* __restrict__ WH, const bf16* __restrict__ WL,
             const float* __restrict__ bias,
             const bf16* __restrict__ resH, const bf16* __restrict__ resL,
             float* __restrict__ Cf, bf16* __restrict__ CH, bf16* __restrict__ CL,
             int K, int N, int act)
{
    extern __shared__ char sm[];
    const uint32_t sbase = smem_u32(sm);
    const int tid = threadIdx.x, lane = tid&31, wid = tid>>5;
    const int gid = lane>>2, tq = lane&3;
    const int wm = wid&1, wn = wid>>1;
    const int m0 = blockIdx.y*BM, n0 = blockIdx.x*BN;
    const bf16* Ah = AHg + (size_t)m0*K;
    const bf16* Al = ALg + (size_t)m0*K;
    const bf16* Bh = WH + (size_t)n0*K;
    const bf16* Bl = WL + (size_t)n0*K;
    const int KT = K/BK;

    const int lrow = tid>>2, lc = tid&3;
    auto LOAD = [&](int kt){
        uint32_t st = sbase + (kt&1)*STG;
#pragma unroll
        for (int i=0;i<2;i++){
            int row = lrow + i*64;
            uint32_t off = (uint32_t)row*SROW + lc*16;
            size_t go = (size_t)row*K + kt*BK + lc*8;
            cpa16(st+off, Ah+go);
            cpa16(st+OPSZ+off, Al+go);
            cpa16(st+2*OPSZ+off, Bh+go);
            cpa16(st+3*OPSZ+off, Bl+go);
        }
        asm volatile("cp.async.commit_group;" ::: "memory");
    };
    const uint32_t aoff = (uint32_t)((wm*64 + (lane&15))*SROW + ((lane>>4)*16));
    const uint32_t boff = (uint32_t)((wn*32 + ((lane>>4)*8) + (lane&7))*SROW + (((lane>>3)&1)*16));

    float acc[4][4][4] = {};
    LOAD(0);
    for (int kt=0; kt<KT; kt++){
        if (kt+1 < KT) LOAD(kt+1);
        if (kt+1 < KT) asm volatile("cp.async.wait_group 1;" ::: "memory");
        else           asm volatile("cp.async.wait_group 0;" ::: "memory");
        __syncthreads();
        const uint32_t st = sbase + (kt&1)*STG;
#pragma unroll
        for (int k16=0; k16<2; k16++){
            const uint32_t ko = k16*32;
            uint32_t ah[4][4], al[4][4];
#pragma unroll
            for (int i=0;i<4;i++){
                ldm_x4(ah[i], st + aoff + i*16*SROW + ko);
                ldm_x4(al[i], st + OPSZ + aoff + i*16*SROW + ko);
            }
#pragma unroll
            for (int jj=0; jj<2; jj++){
                uint32_t bh4[4], bl4[4];
                ldm_x4(bh4, st + 2*OPSZ + boff + jj*16*SROW + ko);
                ldm_x4(bl4, st + 3*OPSZ + boff + jj*16*SROW + ko);
#pragma unroll
                for (int jh=0; jh<2; jh++){
                    const int j = jj*2 + jh;
                    uint32_t b0 = bh4[2*jh], b1 = bh4[2*jh+1];
                    uint32_t c0 = bl4[2*jh], c1 = bl4[2*jh+1];
#pragma unroll
                    for (int i=0;i<4;i++){
                        mma_bf16(acc[i][j], ah[i], b0, b1);
                        mma_bf16(acc[i][j], ah[i], c0, c1);
                        mma_bf16(acc[i][j], al[i], b0, b1);
                    }
                }
            }
        }
        __syncthreads();
    }
#pragma unroll
    for (int i=0;i<4;i++){
        const int r0 = m0 + wm*64 + i*16 + gid;
#pragma unroll
        for (int j=0;j<4;j++){
            const int c = n0 + wn*32 + j*8 + 2*tq;
            float b0 = bias[c], b1 = bias[c+1];
            float v[4] = {acc[i][j][0]+b0, acc[i][j][1]+b1, acc[i][j][2]+b0, acc[i][j][3]+b1};
            if (resH){
                uint32_t rh0 = *(const uint32_t*)(resH + (size_t)r0*N + c);
                uint32_t rl0u = *(const uint32_t*)(resL + (size_t)r0*N + c);
                uint32_t rh1 = *(const uint32_t*)(resH + (size_t)(r0+8)*N + c);
                uint32_t rl1u = *(const uint32_t*)(resL + (size_t)(r0+8)*N + c);
                bf162 h0 = *(bf162*)&rh0, l0v = *(bf162*)&rl0u;
                bf162 h1 = *(bf162*)&rh1, l1v = *(bf162*)&rl1u;
                v[0] += bff(h0.x)+bff(l0v.x); v[1] += bff(h0.y)+bff(l0v.y);
                v[2] += bff(h1.x)+bff(l1v.x); v[3] += bff(h1.y)+bff(l1v.y);
            }
            if (act==1){
#pragma unroll
                for (int u=0;u<4;u++) v[u] = v[u]>0.f ? v[u] : 0.01f*v[u];
            } else if (act==2){
#pragma unroll
                for (int u=0;u<4;u++) v[u] = 2.f*(v[u]>0.f ? v[u] : 0.01f*v[u]);
            }
            if (Cf){
                *(float2*)(Cf + (size_t)r0*N + c)     = make_float2(v[0], v[1]);
                *(float2*)(Cf + (size_t)(r0+8)*N + c) = make_float2(v[2], v[3]);
            }
            if (CH){
                bf16 h0=bfh(v[0]), h1=bfh(v[1]), h2=bfh(v[2]), h3=bfh(v[3]);
                *(uint32_t*)(CH + (size_t)r0*N + c)     = pack2(h0,h1);
                *(uint32_t*)(CH + (size_t)(r0+8)*N + c) = pack2(h2,h3);
                *(uint32_t*)(CL + (size_t)r0*N + c) =
                    pack2(bfh(v[0]-bff(h0)), bfh(v[1]-bff(h1)));
                *(uint32_t*)(CL + (size_t)(r0+8)*N + c) =
                    pack2(bfh(v[2]-bff(h2)), bfh(v[3]-bff(h3)));
            }
        }
    }
}

// ---------------- LayerNorm: 256 threads, 2 rows/block ----------------
__global__ void ln_kernel(const float* __restrict__ X, const float* __restrict__ w,
                          const float* __restrict__ b,
                          bf16* __restrict__ YH, bf16* __restrict__ YL)
{
    const int tid = threadIdx.x;
    const int sub = tid >> 7;
    const int t   = tid & 127;
    const int row = blockIdx.x*2 + sub;
    float4 v = ((const float4*)(X + (size_t)row*512))[t];
    float s = v.x+v.y+v.z+v.w, ss = v.x*v.x+v.y*v.y+v.z*v.z+v.w*v.w;
#pragma unroll
    for (int o=16;o>0;o>>=1){ s+=__shfl_xor_sync(~0u,s,o); ss+=__shfl_xor_sync(~0u,ss,o); }
    __shared__ float rs[2][4], rss[2][4];
    int wd=(t>>5), ln=t&31;
    if (ln==0){ rs[sub][wd]=s; rss[sub][wd]=ss; }
    __syncthreads();
    s=rs[sub][0]+rs[sub][1]+rs[sub][2]+rs[sub][3];
    ss=rss[sub][0]+rss[sub][1]+rss[sub][2]+rss[sub][3];
    float mean=s*(1.f/512.f), var=ss*(1.f/512.f)-mean*mean, inv=rsqrtf(var+1e-5f);
    float4 wv=((const float4*)w)[t], bv=((const float4*)b)[t], y;
    y.x=(v.x-mean)*inv*wv.x+bv.x; y.y=(v.y-mean)*inv*wv.y+bv.y;
    y.z=(v.z-mean)*inv*wv.z+bv.z; y.w=(v.w-mean)*inv*wv.w+bv.w;
    bf16 h0=bfh(y.x), h1=bfh(y.y), h2=bfh(y.z), h3=bfh(y.w);
    uint32_t* HH = (uint32_t*)(YH + (size_t)row*512);
    uint32_t* LL = (uint32_t*)(YL + (size_t)row*512);
    HH[t*2]   = pack2(h0,h1);
    HH[t*2+1] = pack2(h2,h3);
    LL[t*2]   = pack2(bfh(y.x-bff(h0)), bfh(y.y-bff(h1)));
    LL[t*2+1] = pack2(bfh(y.z-bff(h2)), bfh(y.w-bff(h3)));
}

// ---------------- attention: 2 q-tiles/block, cp.async double-buffered K/V --
// regions: stage0 K/V = 0..3, stage1 K/V = 4..7. Q (2 tiles) staged via 4..7.
#define AST 72
#define RSZ (64*AST*2)
#define ATT_SMEM (8*RSZ)

__global__ __launch_bounds__(128)
void attn_mma(const bf16* __restrict__ Qh, const bf16* __restrict__ Ql, int qs,
              const bf16* __restrict__ Kh, const bf16* __restrict__ Kl, int ks,
              const bf16* __restrict__ Vh, const bf16* __restrict__ Vl, int vs,
              bf16* __restrict__ OH, bf16* __restrict__ OL, int causal)
{
    extern __shared__ char smc[];
    const uint32_t sb = smem_u32(smc);
    const int qp = causal ? (int)(gridDim.x - 1 - blockIdx.x) : (int)blockIdx.x;
    const int qt0 = qp*2;                 // halves: qt0, qt0+1
    const int bh = blockIdx.y;
    const int b = bh >> 3, h = bh & 7;
    const int tid = threadIdx.x, lane = tid & 31, wid = tid >> 5;
    const int gid = lane >> 2, tq = lane & 3;
    const size_t krowb = (size_t)b*512 + h*64;
    const int ktmax = causal ? (qt0+1) : 7;

    auto LOADKV = [&](int kt){
        const uint32_t st = sb + (kt&1)*(4*RSZ);
        const size_t krow = krowb + kt*8;
        for (int i = tid; i < 512; i += 128){
            int r = i >> 3, cc = (i & 7) * 8;
            size_t gk = (krow + (r>>3))*ks + (r&7)*64 + cc;
            size_t gv = (krow + (r>>3))*vs + (r&7)*64 + cc;
            uint32_t off = (uint32_t)(r*AST + cc)*2;
            cpa16(st + off,         Kh + gk);
            cpa16(st + RSZ + off,   Kl + gk);
            cpa16(st + 2*RSZ + off, Vh + gv);
            cpa16(st + 3*RSZ + off, Vl + gv);
        }
        asm volatile("cp.async.commit_group;" ::: "memory");
    };

    // prologue: both Q tiles -> regions 4..7 ; K/V kt0 -> stage0
    for (int i = tid; i < 1024; i += 128){
        int hf = i >> 9, r = (i >> 3) & 63, cc = (i & 7) * 8;
        size_t g = ((size_t)(krowb + (size_t)(qt0+hf)*8 + (r>>3)))*qs + (r&7)*64 + cc;
        uint32_t off = (uint32_t)(r*AST + cc)*2;
        cpa16(sb + (4+2*hf)*RSZ + off, Qh + g);
        cpa16(sb + (5+2*hf)*RSZ + off, Ql + g);
    }
    asm volatile("cp.async.commit_group;" ::: "memory");
    LOADKV(0);
    asm volatile("cp.async.wait_group 0;" ::: "memory");
    __syncthreads();

    const uint32_t qlane = (uint32_t)(((wid*16 + (lane&15))*AST + (lane>>4)*8)*2);
    const uint32_t krel  = (uint32_t)(((((lane>>4)*8) + (lane&7))*AST + ((lane>>3)&1)*8)*2);
    const uint32_t vrel  = (uint32_t)(((((lane&7) + ((lane>>3)&1)*8)*AST) + (lane>>4)*8)*2);

    uint32_t qfh[2][4][4], qfl[2][4][4];
#pragma unroll
    for (int hf=0; hf<2; hf++)
#pragma unroll
        for (int g=0; g<4; g++){
            ldm_x4(qfh[hf][g], sb + (4+2*hf)*RSZ + qlane + g*32);
            ldm_x4(qfl[hf][g], sb + (5+2*hf)*RSZ + qlane + g*32);
        }
    __syncthreads();   // Q extracted everywhere before stage1 overwrite

    float m[2][2], l[2][2];
    m[0][0]=m[0][1]=m[1][0]=m[1][1]=-INFINITY;
    l[0][0]=l[0][1]=l[1][0]=l[1][1]=0.f;
    float acc[2][8][4] = {};

    for (int kt=0; kt<=ktmax; kt++){
        if (kt > 0){
            asm volatile("cp.async.wait_group 0;" ::: "memory");
            __syncthreads();
        }
        if (kt+1 <= ktmax) LOADKV(kt+1);
        const uint32_t st = sb + (kt&1)*(4*RSZ);

#pragma unroll
        for (int hf=0; hf<2; hf++){
            const int qtH = qt0 + hf;
            if (causal && kt > qtH) continue;

            float s[8][4] = {};
#pragma unroll
            for (int g=0; g<4; g++){
#pragma unroll
                for (int kk=0; kk<4; kk++){
                    uint32_t bk[4], bkl[4];
                    ldm_x4(bk,  st + krel + g*(16*AST*2) + kk*32);
                    ldm_x4(bkl, st + RSZ + krel + g*(16*AST*2) + kk*32);
                    mma_bf16(s[2*g],   qfh[hf][kk], bk[0],  bk[1]);
                    mma_bf16(s[2*g],   qfh[hf][kk], bkl[0], bkl[1]);
                    mma_bf16(s[2*g],   qfl[hf][kk], bk[0],  bk[1]);
                    mma_bf16(s[2*g+1], qfh[hf][kk], bk[2],  bk[3]);
                    mma_bf16(s[2*g+1], qfh[hf][kk], bkl[2], bkl[3]);
                    mma_bf16(s[2*g+1], qfl[hf][kk], bk[2],  bk[3]);
                }
            }

            const int rl0 = wid*16 + gid;
            float mx0=-INFINITY, mx1=-INFINITY;
#pragma unroll
            for (int j=0; j<8; j++){
#pragma unroll
                for (int c=0; c<4; c++) s[j][c] *= 0.03125f;
                if (causal && kt == qtH){
                    int col = j*8 + 2*tq;
                    if (col   > rl0)   s[j][0] = -1e9f;
                    if (col+1 > rl0)   s[j][1] = -1e9f;
                    if (col   > rl0+8) s[j][2] = -1e9f;
                    if (col+1 > rl0+8) s[j][3] = -1e9f;
                }
                mx0 = fmaxf(mx0, fmaxf(s[j][0], s[j][1]));
                mx1 = fmaxf(mx1, fmaxf(s[j][2], s[j][3]));
            }
            mx0 = fmaxf(mx0, __shfl_xor_sync(~0u, mx0, 1));
            mx0 = fmaxf(mx0, __shfl_xor_sync(~0u, mx0, 2));
            mx1 = fmaxf(mx1, __shfl_xor_sync(~0u, mx1, 1));
            mx1 = fmaxf(mx1, __shfl_xor_sync(~0u, mx1, 2));
            float mn0 = fmaxf(m[hf][0], mx0), mn1 = fmaxf(m[hf][1], mx1);
            float f0 = __expf(m[hf][0] - mn0), f1 = __expf(m[hf][1] - mn1);
            m[hf][0] = mn0; m[hf][1] = mn1; l[hf][0] *= f0; l[hf][1] *= f1;
#pragma unroll
            for (int j=0; j<8; j++){
                s[j][0] = __expf(s[j][0]-mn0); s[j][1] = __expf(s[j][1]-mn0);
                s[j][2] = __expf(s[j][2]-mn1); s[j][3] = __expf(s[j][3]-mn1);
                l[hf][0] += s[j][0] + s[j][1];
                l[hf][1] += s[j][2] + s[j][3];
                acc[hf][j][0]*=f0; acc[hf][j][1]*=f0; acc[hf][j][2]*=f1; acc[hf][j][3]*=f1;
            }

#pragma unroll
            for (int g=0; g<4; g++){
                float* t0 = s[2*g]; float* t1 = s[2*g+1];
                bf16 h00=bfh(t0[0]), h01=bfh(t0[1]), h02=bfh(t0[2]), h03=bfh(t0[3]);
                bf16 h10=bfh(t1[0]), h11=bfh(t1[1]), h12=bfh(t1[2]), h13=bfh(t1[3]);
                uint32_t aph[4] = { pack2(h00,h01), pack2(h02,h03), pack2(h10,h11), pack2(h12,h13) };
                uint32_t apl[4] = {
                    pack2(bfh(t0[0]-bff(h00)), bfh(t0[1]-bff(h01))),
                    pack2(bfh(t0[2]-bff(h02)), bfh(t0[3]-bff(h03))),
                    pack2(bfh(t1[0]-bff(h10)), bfh(t1[1]-bff(h11))),
                    pack2(bfh(t1[2]-bff(h12)), bfh(t1[3]-bff(h13))) };
#pragma unroll
                for (int jj=0; jj<4; jj++){
                    uint32_t bv[4], bvl[4];
                    ldm_x4t(bv,  st + 2*RSZ + vrel + g*(16*AST*2) + jj*32);
                    ldm_x4t(bvl, st + 3*RSZ + vrel + g*(16*AST*2) + jj*32);
                    mma_bf16(acc[hf][2*jj],   aph, bv[0],  bv[1]);
                    mma_bf16(acc[hf][2*jj],   aph, bvl[0], bvl[1]);
                    mma_bf16(acc[hf][2*jj],   apl, bv[0],  bv[1]);
                    mma_bf16(acc[hf][2*jj+1], aph, bv[2],  bv[3]);
                    mma_bf16(acc[hf][2*jj+1], aph, bvl[2], bvl[3]);
                    mma_bf16(acc[hf][2*jj+1], apl, bv[2],  bv[3]);
                }
            }
        }
    }

#pragma unroll
    for (int hf=0; hf<2; hf++){
        float L0 = l[hf][0], L1 = l[hf][1];
        L0 += __shfl_xor_sync(~0u, L0, 1); L0 += __shfl_xor_sync(~0u, L0, 2);
        L1 += __shfl_xor_sync(~0u, L1, 1); L1 += __shfl_xor_sync(~0u, L1, 2);
        float inv0 = 1.f/L0, inv1 = 1.f/L1;
        const size_t orow = krowb + (size_t)(qt0+hf)*8 + wid*2;
#pragma unroll
        for (int j=0; j<8; j++){
            int col = gid*64 + j*8 + 2*tq;
            float o0 = acc[hf][j][0]*inv0, o1 = acc[hf][j][1]*inv0;
            float o2 = acc[hf][j][2]*inv1, o3 = acc[hf][j][3]*inv1;
            bf16 h0=bfh(o0), h1=bfh(o1), h2=bfh(o2), h3=bfh(o3);
            *(uint32_t*)(OH + orow*512 + col)     = pack2(h0,h1);
            *(uint32_t*)(OH + (orow+1)*512 + col) = pack2(h2,h3);
            *(uint32_t*)(OL + orow*512 + col)     = pack2(bfh(o0-bff(h0)), bfh(o1-bff(h1)));
            *(uint32_t*)(OL + (orow+1)*512 + col) = pack2(bfh(o2-bff(h2)), bfh(o3-bff(h3)));
        }
    }
}

// ---------------- orchestration ----------------
extern "C" void kernel_launch(void* const* d_in, const int* in_sizes, int n_in,
                              void* d_out, int out_size)
{
    const float* memory   = (const float*)d_in[0];
    const float* target   = (const float*)d_in[1];
    const float* expand_w = (const float*)d_in[3];
    const float* expand_b = (const float*)d_in[4];
    const float* ln_w     = (const float*)d_in[5];
    const float* ln_b     = (const float*)d_in[6];
    const float* attn_w   = (const float*)d_in[7];
    const float* attn_b   = (const float*)d_in[8];
    const float* ff_w1    = (const float*)d_in[9];
    const float* ff_b1    = (const float*)d_in[10];
    const float* ff_w2    = (const float*)d_in[11];
    const float* ff_b2    = (const float*)d_in[12];
    float* out = (float*)d_out;

    float *t;
    bf16 *xh,*xl,*qkvh,*qkvl,*kvh,*kvl,*aoh,*aol,*memh,*meml,*ffh,*ffl,*inh,*inl;
    bf16 *whA,*wlA,*wh1,*wl1,*wh2,*wl2,*whe,*wle;
    cudaGetSymbolAddress((void**)&t,  g_t);
    cudaGetSymbolAddress((void**)&xh, g_xh);
    cudaGetSymbolAddress((void**)&xl, g_xl);
    cudaGetSymbolAddress((void**)&qkvh,g_qkvh);
    cudaGetSymbolAddress((void**)&qkvl,g_qkvl);
    cudaGetSymbolAddress((void**)&kvh,g_kvh);
    cudaGetSymbolAddress((void**)&kvl,g_kvl);
    cudaGetSymbolAddress((void**)&aoh,g_aoh);
    cudaGetSymbolAddress((void**)&aol,g_aol);
    cudaGetSymbolAddress((void**)&memh,g_memh);
    cudaGetSymbolAddress((void**)&meml,g_meml);
    cudaGetSymbolAddress((void**)&ffh,g_ffh);
    cudaGetSymbolAddress((void**)&ffl,g_ffl);
    cudaGetSymbolAddress((void**)&inh,g_inh);
    cudaGetSymbolAddress((void**)&inl,g_inl);
    cudaGetSymbolAddress((void**)&whA,g_wh_attn);
    cudaGetSymbolAddress((void**)&wlA,g_wl_attn);
    cudaGetSymbolAddress((void**)&wh1,g_wh_ff1);
    cudaGetSymbolAddress((void**)&wl1,g_wl_ff1);
    cudaGetSymbolAddress((void**)&wh2,g_wh_ff2);
    cudaGetSymbolAddress((void**)&wl2,g_wl_ff2);
    cudaGetSymbolAddress((void**)&whe,g_wh_exp);
    cudaGetSymbolAddress((void**)&wle,g_wl_exp);

    cudaFuncSetAttribute(tc_gemm,  cudaFuncAttributeMaxDynamicSharedMemorySize, GEMM_SMEM);
    cudaFuncSetAttribute(attn_mma, cudaFuncAttributeMaxDynamicSharedMemorySize, ATT_SMEM);

    tsplit_kernel<<<dim3(16,16,48), dim3(32,8)>>>(attn_w,   whA, wlA, 512, 512);
    tsplit_kernel<<<dim3(64,16,6),  dim3(32,8)>>>(ff_w1,    wh1, wl1, 512, 2048);
    tsplit_kernel<<<dim3(16,64,6),  dim3(32,8)>>>(ff_w2,    wh2, wl2, 2048, 512);
    tsplit_kernel<<<dim3(16,4,1),   dim3(32,8)>>>(expand_w, whe, wle, 128, 512);
    csplit_kernel<<<MROWS*128/256, 256>>>(memory, inh, inl, MROWS*128);

    auto G = [&](const bf16* AH, const bf16* AL, const bf16* WH, const bf16* WL,
                 const float* bi, const bf16* rH, const bf16* rL,
                 float* Cf, bf16* CH, bf16* CL, int K, int N, int act){
        tc_gemm<<<dim3(N/BN, MROWS/BM), 256, GEMM_SMEM>>>(AH, AL, WH, WL, bi, rH, rL, Cf, CH, CL, K, N, act);
    };
    const dim3 ga(4, 128);   // 2 q-tiles per block

    G(inh, inl, whe, wle, expand_b, nullptr, nullptr, nullptr, memh, meml, 128, 512, 1);

    const float* tin = target;
    for (int l=0; l<NLAYERS; l++){
        const size_t wo = (size_t)l*8*262144;
        const float* ab = attn_b + (size_t)l*8*DDIM;
        const float* lw = ln_w + (size_t)l*3*DDIM;
        const float* lb = ln_b + (size_t)l*3*DDIM;

        // self-attention (fused QKV)
        ln_kernel<<<MROWS/2,256>>>(tin, lw, lb, xh, xl);
        G(xh, xl, whA+wo, wlA+wo, ab, nullptr, nullptr, nullptr, qkvh, qkvl, 512, 1536, 0);
        attn_mma<<<ga,128,ATT_SMEM>>>(qkvh, qkvl, 1536, qkvh+512, qkvl+512, 1536,
                                      qkvh+1024, qkvl+1024, 1536, aoh, aol, 1);
        G(aoh, aol, whA+wo+3ull*262144, wlA+wo+3ull*262144, ab+3*DDIM, xh, xl, t, nullptr, nullptr, 512, 512, 0);

        // cross-attention (fused KV)
        ln_kernel<<<MROWS/2,256>>>(t, lw+DDIM, lb+DDIM, xh, xl);
        G(xh, xl, whA+wo+4ull*262144, wlA+wo+4ull*262144, ab+4*DDIM, nullptr, nullptr, nullptr, qkvh, qkvl, 512, 512, 0);
        G(memh, meml, whA+wo+5ull*262144, wlA+wo+5ull*262144, ab+5*DDIM, nullptr, nullptr, nullptr, kvh, kvl, 512, 1024, 0);
        attn_mma<<<ga,128,ATT_SMEM>>>(qkvh, qkvl, 512, kvh, kvl, 1024,
                                      kvh+512, kvl+512, 1024, aoh, aol, 0);
        G(aoh, aol, whA+wo+7ull*262144, wlA+wo+7ull*262144, ab+7*DDIM, xh, xl, t, nullptr, nullptr, 512, 512, 0);

        // feed-forward
        ln_kernel<<<MROWS/2,256>>>(t, lw+2*DDIM, lb+2*DDIM, xh, xl);
        G(xh, xl, wh1+(size_t)l*DDIM*FFF, wl1+(size_t)l*DDIM*FFF, ff_b1+(size_t)l*FFF,
          nullptr, nullptr, nullptr, ffh, ffl, 512, 2048, 1);
        float* dst = (l==NLAYERS-1) ? out : t;
        G(ffh, ffl, wh2+(size_t)l*FFF*DDIM, wl2+(size_t)l*FFF*DDIM, ff_b2+(size_t)l*DDIM,
          nullptr, nullptr, dst, nullptr, nullptr, 2048, 512, 2);
        tin = t;
    }
}

// round 15
// speedup vs baseline: 1.0097x; 1.0097x over previous
#include <cuda_runtime.h>
#include <cuda_bf16.h>
#include <cstdint>
#include <math.h>

#define BB 16
#define DDIM 512
#define FFF 2048
#define NLAYERS 6
#define MROWS (BB*512)

typedef __nv_bfloat16 bf16;
typedef __nv_bfloat162 bf162;

// ---------------- scratch ----------------
__device__ __align__(256) float g_t [MROWS*DDIM];
__device__ __align__(256) bf16 g_xh [MROWS*DDIM];
__device__ __align__(256) bf16 g_xl [MROWS*DDIM];
__device__ __align__(256) bf16 g_qkvh[MROWS*1536];
__device__ __align__(256) bf16 g_qkvl[MROWS*1536];
__device__ __align__(256) bf16 g_kvh [MROWS*1024];
__device__ __align__(256) bf16 g_kvl [MROWS*1024];
__device__ __align__(256) bf16 g_aoh[MROWS*DDIM];
__device__ __align__(256) bf16 g_aol[MROWS*DDIM];
__device__ __align__(256) bf16 g_memh[MROWS*DDIM];
__device__ __align__(256) bf16 g_meml[MROWS*DDIM];
__device__ __align__(256) bf16 g_ffh[MROWS*FFF];
__device__ __align__(256) bf16 g_ffl[MROWS*FFF];
__device__ __align__(256) bf16 g_inh[MROWS*128];
__device__ __align__(256) bf16 g_inl[MROWS*128];
__device__ __align__(256) bf16 g_wh_attn[48*512*512];
__device__ __align__(256) bf16 g_wl_attn[48*512*512];
__device__ __align__(256) bf16 g_wh_ff1 [6*2048*512];
__device__ __align__(256) bf16 g_wl_ff1 [6*2048*512];
__device__ __align__(256) bf16 g_wh_ff2 [6*512*2048];
__device__ __align__(256) bf16 g_wl_ff2 [6*512*2048];
__device__ __align__(256) bf16 g_wh_exp [512*128];
__device__ __align__(256) bf16 g_wl_exp [512*128];

// ---------------- helpers ----------------
__device__ __forceinline__ uint32_t smem_u32(const void* p){
    uint32_t a; asm("{ .reg .u64 t; cvta.to.shared.u64 t, %1; cvt.u32.u64 %0, t; }":"=r"(a):"l"(p)); return a;
}
__device__ __forceinline__ void ldm_x4(uint32_t* r, uint32_t addr){
    asm volatile("ldmatrix.sync.aligned.m8n8.x4.shared.b16 {%0,%1,%2,%3}, [%4];"
        : "=r"(r[0]),"=r"(r[1]),"=r"(r[2]),"=r"(r[3]) : "r"(addr));
}
__device__ __forceinline__ void ldm_x4t(uint32_t* r, uint32_t addr){
    asm volatile("ldmatrix.sync.aligned.m8n8.x4.trans.shared.b16 {%0,%1,%2,%3}, [%4];"
        : "=r"(r[0]),"=r"(r[1]),"=r"(r[2]),"=r"(r[3]) : "r"(addr));
}
__device__ __forceinline__ void cpa16(uint32_t dst, const void* src){
    asm volatile("cp.async.cg.shared.global [%0], [%1], 16;" :: "r"(dst), "l"(src));
}
__device__ __forceinline__ void mma_bf16(float* d, const uint32_t* a, uint32_t b0, uint32_t b1){
    asm volatile(
        "mma.sync.aligned.m16n8k16.row.col.f32.bf16.bf16.f32 "
        "{%0,%1,%2,%3}, {%4,%5,%6,%7}, {%8,%9}, {%0,%1,%2,%3};"
        : "+f"(d[0]), "+f"(d[1]), "+f"(d[2]), "+f"(d[3])
        : "r"(a[0]), "r"(a[1]), "r"(a[2]), "r"(a[3]), "r"(b0), "r"(b1));
}
__device__ __forceinline__ uint32_t pack2(bf16 a, bf16 b){ bf162 h; h.x=a; h.y=b; return *(uint32_t*)&h; }
__device__ __forceinline__ bf16 bfh(float v){ return __float2bfloat16_rn(v); }
__device__ __forceinline__ float bff(bf16 v){ return __bfloat162float(v); }

// ---------------- transpose + split weights ----------------
__global__ void tsplit_kernel(const float* __restrict__ W, bf16* __restrict__ Hi,
                              bf16* __restrict__ Lo, int K, int N)
{
    __shared__ float t[32][33];
    const float* Wm = W + (size_t)blockIdx.z*K*N;
    bf16* Hm = Hi + (size_t)blockIdx.z*K*N;
    bf16* Lm = Lo + (size_t)blockIdx.z*K*N;
    int n0=blockIdx.x*32, k0=blockIdx.y*32, x=threadIdx.x, y=threadIdx.y;
#pragma unroll
    for (int i=0;i<32;i+=8) t[y+i][x] = Wm[(size_t)(k0+y+i)*N + n0+x];
    __syncthreads();
#pragma unroll
    for (int i=0;i<32;i+=8){
        float v = t[x][y+i];
        bf16 h = bfh(v);
        Hm[(size_t)(n0+y+i)*K + k0+x] = h;
        Lm[(size_t)(n0+y+i)*K + k0+x] = bfh(v - bff(h));
    }
}
__global__ void csplit_kernel(const float* __restrict__ X, bf16* __restrict__ H,
                              bf16* __restrict__ L, int n)
{
    int i = blockIdx.x*blockDim.x + threadIdx.x;
    if (i < n){
        float v = X[i];
        bf16 h = bfh(v);
        H[i] = h; L[i] = bfh(v - bff(h));
    }
}

// ---------------- GEMM (R10 proven core; bf16 hi/lo residual) ----------------
#define BM 128
#define BN 128
#define BK 32
#define SROW 80
#define OPSZ (128*SROW)
#define STG (4*OPSZ)
#define GEMM_SMEM (2*STG)

__global__ __launch_bounds__(256, 2)
void tc_gemm(const bf16* __restrict__ AHg, const bf16* __restrict__ ALg,
             const bf16* __restrict__ WH, const bf16* __restrict__ WL,
             const float* __restrict__ bias,
             const bf16* __restrict__ resH, const bf16* __restrict__ resL,
             float* __restrict__ Cf, bf16* __restrict__ CH, bf16* __restrict__ CL,
             int K, int N, int act)
{
    extern __shared__ char sm[];
    const uint32_t sbase = smem_u32(sm);
    const int tid = threadIdx.x, lane = tid&31, wid = tid>>5;
    const int gid = lane>>2, tq = lane&3;
    const int wm = wid&1, wn = wid>>1;
    const int m0 = blockIdx.y*BM, n0 = blockIdx.x*BN;
    const bf16* Ah = AHg + (size_t)m0*K;
    const bf16* Al = ALg + (size_t)m0*K;
    const bf16* Bh = WH + (size_t)n0*K;
    const bf16* Bl = WL + (size_t)n0*K;
    const int KT = K/BK;

    const int lrow = tid>>2, lc = tid&3;
    auto LOAD = [&](int kt){
        uint32_t st = sbase + (kt&1)*STG;
#pragma unroll
        for (int i=0;i<2;i++){
            int row = lrow + i*64;
            uint32_t off = (uint32_t)row*SROW + lc*16;
            size_t go = (size_t)row*K + kt*BK + lc*8;
            cpa16(st+off, Ah+go);
            cpa16(st+OPSZ+off, Al+go);
            cpa16(st+2*OPSZ+off, Bh+go);
            cpa16(st+3*OPSZ+off, Bl+go);
        }
        asm volatile("cp.async.commit_group;" ::: "memory");
    };
    const uint32_t aoff = (uint32_t)((wm*64 + (lane&15))*SROW + ((lane>>4)*16));
    const uint32_t boff = (uint32_t)((wn*32 + ((lane>>4)*8) + (lane&7))*SROW + (((lane>>3)&1)*16));

    float acc[4][4][4] = {};
    LOAD(0);
    for (int kt=0; kt<KT; kt++){
        if (kt+1 < KT) LOAD(kt+1);
        if (kt+1 < KT) asm volatile("cp.async.wait_group 1;" ::: "memory");
        else           asm volatile("cp.async.wait_group 0;" ::: "memory");
        __syncthreads();
        const uint32_t st = sbase + (kt&1)*STG;
#pragma unroll
        for (int k16=0; k16<2; k16++){
            const uint32_t ko = k16*32;
            uint32_t ah[4][4], al[4][4];
#pragma unroll
            for (int i=0;i<4;i++){
                ldm_x4(ah[i], st + aoff + i*16*SROW + ko);
                ldm_x4(al[i], st + OPSZ + aoff + i*16*SROW + ko);
            }
#pragma unroll
            for (int jj=0; jj<2; jj++){
                uint32_t bh4[4], bl4[4];
                ldm_x4(bh4, st + 2*OPSZ + boff + jj*16*SROW + ko);
                ldm_x4(bl4, st + 3*OPSZ + boff + jj*16*SROW + ko);
#pragma unroll
                for (int jh=0; jh<2; jh++){
                    const int j = jj*2 + jh;
                    uint32_t b0 = bh4[2*jh], b1 = bh4[2*jh+1];
                    uint32_t c0 = bl4[2*jh], c1 = bl4[2*jh+1];
#pragma unroll
                    for (int i=0;i<4;i++){
                        mma_bf16(acc[i][j], ah[i], b0, b1);
                        mma_bf16(acc[i][j], ah[i], c0, c1);
                        mma_bf16(acc[i][j], al[i], b0, b1);
                    }
                }
            }
        }
        __syncthreads();
    }
#pragma unroll
    for (int i=0;i<4;i++){
        const int r0 = m0 + wm*64 + i*16 + gid;
#pragma unroll
        for (int j=0;j<4;j++){
            const int c = n0 + wn*32 + j*8 + 2*tq;
            float b0 = bias[c], b1 = bias[c+1];
            float v[4] = {acc[i][j][0]+b0, acc[i][j][1]+b1, acc[i][j][2]+b0, acc[i][j][3]+b1};
            if (resH){
                uint32_t rh0 = *(const uint32_t*)(resH + (size_t)r0*N + c);
                uint32_t rl0u = *(const uint32_t*)(resL + (size_t)r0*N + c);
                uint32_t rh1 = *(const uint32_t*)(resH + (size_t)(r0+8)*N + c);
                uint32_t rl1u = *(const uint32_t*)(resL + (size_t)(r0+8)*N + c);
                bf162 h0 = *(bf162*)&rh0, l0v = *(bf162*)&rl0u;
                bf162 h1 = *(bf162*)&rh1, l1v = *(bf162*)&rl1u;
                v[0] += bff(h0.x)+bff(l0v.x); v[1] += bff(h0.y)+bff(l0v.y);
                v[2] += bff(h1.x)+bff(l1v.x); v[3] += bff(h1.y)+bff(l1v.y);
            }
            if (act==1){
#pragma unroll
                for (int u=0;u<4;u++) v[u] = v[u]>0.f ? v[u] : 0.01f*v[u];
            } else if (act==2){
#pragma unroll
                for (int u=0;u<4;u++) v[u] = 2.f*(v[u]>0.f ? v[u] : 0.01f*v[u]);
            }
            if (Cf){
                *(float2*)(Cf + (size_t)r0*N + c)     = make_float2(v[0], v[1]);
                *(float2*)(Cf + (size_t)(r0+8)*N + c) = make_float2(v[2], v[3]);
            }
            if (CH){
                bf16 h0=bfh(v[0]), h1=bfh(v[1]), h2=bfh(v[2]), h3=bfh(v[3]);
                *(uint32_t*)(CH + (size_t)r0*N + c)     = pack2(h0,h1);
                *(uint32_t*)(CH + (size_t)(r0+8)*N + c) = pack2(h2,h3);
                *(uint32_t*)(CL + (size_t)r0*N + c) =
                    pack2(bfh(v[0]-bff(h0)), bfh(v[1]-bff(h1)));
                *(uint32_t*)(CL + (size_t)(r0+8)*N + c) =
                    pack2(bfh(v[2]-bff(h2)), bfh(v[3]-bff(h3)));
            }
        }
    }
}

// ---------------- LayerNorm: 256 threads, 2 rows/block ----------------
__global__ void ln_kernel(const float* __restrict__ X, const float* __restrict__ w,
                          const float* __restrict__ b,
                          bf16* __restrict__ YH, bf16* __restrict__ YL)
{
    const int tid = threadIdx.x;
    const int sub = tid >> 7;
    const int t   = tid & 127;
    const int row = blockIdx.x*2 + sub;
    float4 v = ((const float4*)(X + (size_t)row*512))[t];
    float s = v.x+v.y+v.z+v.w, ss = v.x*v.x+v.y*v.y+v.z*v.z+v.w*v.w;
#pragma unroll
    for (int o=16;o>0;o>>=1){ s+=__shfl_xor_sync(~0u,s,o); ss+=__shfl_xor_sync(~0u,ss,o); }
    __shared__ float rs[2][4], rss[2][4];
    int wd=(t>>5), ln=t&31;
    if (ln==0){ rs[sub][wd]=s; rss[sub][wd]=ss; }
    __syncthreads();
    s=rs[sub][0]+rs[sub][1]+rs[sub][2]+rs[sub][3];
    ss=rss[sub][0]+rss[sub][1]+rss[sub][2]+rss[sub][3];
    float mean=s*(1.f/512.f), var=ss*(1.f/512.f)-mean*mean, inv=rsqrtf(var+1e-5f);
    float4 wv=((const float4*)w)[t], bv=((const float4*)b)[t], y;
    y.x=(v.x-mean)*inv*wv.x+bv.x; y.y=(v.y-mean)*inv*wv.y+bv.y;
    y.z=(v.z-mean)*inv*wv.z+bv.z; y.w=(v.w-mean)*inv*wv.w+bv.w;
    bf16 h0=bfh(y.x), h1=bfh(y.y), h2=bfh(y.z), h3=bfh(y.w);
    uint32_t* HH = (uint32_t*)(YH + (size_t)row*512);
    uint32_t* LL = (uint32_t*)(YL + (size_t)row*512);
    HH[t*2]   = pack2(h0,h1);
    HH[t*2+1] = pack2(h2,h3);
    LL[t*2]   = pack2(bfh(y.x-bff(h0)), bfh(y.y-bff(h1)));
    LL[t*2+1] = pack2(bfh(y.z-bff(h2)), bfh(y.w-bff(h3)));
}

// ---------------- attention: cp.async double-buffered K/V (R13 proven) ------
#define AST 72
#define RSZ (64*AST*2)
#define ATT_SMEM (8*RSZ)

__global__ __launch_bounds__(128)
void attn_mma(const bf16* __restrict__ Qh, const bf16* __restrict__ Ql, int qs,
              const bf16* __restrict__ Kh, const bf16* __restrict__ Kl, int ks,
              const bf16* __restrict__ Vh, const bf16* __restrict__ Vl, int vs,
              bf16* __restrict__ OH, bf16* __restrict__ OL, int causal)
{
    extern __shared__ char smc[];
    const uint32_t sb = smem_u32(smc);
    const int qt = causal ? (int)(gridDim.x - 1 - blockIdx.x) : (int)blockIdx.x;
    const int bh = blockIdx.y;
    const int b = bh >> 3, h = bh & 7;
    const int tid = threadIdx.x, lane = tid & 31, wid = tid >> 5;
    const int gid = lane >> 2, tq = lane & 3;
    const size_t qrow0 = (size_t)b*512 + h*64 + qt*8;
    const size_t krowb = (size_t)b*512 + h*64;
    const int ktmax = causal ? qt : 7;

    auto LOADKV = [&](int kt){
        const uint32_t st = sb + (kt&1)*(4*RSZ);
        const size_t krow = krowb + kt*8;
        for (int i = tid; i < 512; i += 128){
            int r = i >> 3, cc = (i & 7) * 8;
            size_t gk = (krow + (r>>3))*ks + (r&7)*64 + cc;
            size_t gv = (krow + (r>>3))*vs + (r&7)*64 + cc;
            uint32_t off = (uint32_t)(r*AST + cc)*2;
            cpa16(st + off,         Kh + gk);
            cpa16(st + RSZ + off,   Kl + gk);
            cpa16(st + 2*RSZ + off, Vh + gv);
            cpa16(st + 3*RSZ + off, Vl + gv);
        }
        asm volatile("cp.async.commit_group;" ::: "memory");
    };

    // prologue: Q -> regions 4,5 ; K/V kt0 -> stage0
    for (int i = tid; i < 512; i += 128){
        int r = i >> 3, cc = (i & 7) * 8;
        size_t g = (qrow0 + (r>>3))*qs + (r&7)*64 + cc;
        uint32_t off = (uint32_t)(r*AST + cc)*2;
        cpa16(sb + 4*RSZ + off, Qh + g);
        cpa16(sb + 5*RSZ + off, Ql + g);
    }
    asm volatile("cp.async.commit_group;" ::: "memory");
    LOADKV(0);
    asm volatile("cp.async.wait_group 0;" ::: "memory");
    __syncthreads();

    const uint32_t qlane = (uint32_t)(((wid*16 + (lane&15))*AST + (lane>>4)*8)*2);
    const uint32_t krel  = (uint32_t)(((((lane>>4)*8) + (lane&7))*AST + ((lane>>3)&1)*8)*2);
    const uint32_t vrel  = (uint32_t)(((((lane&7) + ((lane>>3)&1)*8)*AST) + (lane>>4)*8)*2);

    uint32_t qfh[4][4], qfl[4][4];
#pragma unroll
    for (int g=0; g<4; g++){
        ldm_x4(qfh[g], sb + 4*RSZ + qlane + g*32);
        ldm_x4(qfl[g], sb + 5*RSZ + qlane + g*32);
    }
    __syncthreads();   // Q fragments extracted everywhere before stage1 overwrite

    float m0=-INFINITY, m1=-INFINITY, l0=0.f, l1=0.f;
    float acc[8][4] = {};

    for (int kt=0; kt<=ktmax; kt++){
        if (kt > 0){
            asm volatile("cp.async.wait_group 0;" ::: "memory");
            __syncthreads();
        }
        if (kt+1 <= ktmax) LOADKV(kt+1);
        const uint32_t st = sb + (kt&1)*(4*RSZ);

        // S = Q K^T (3-term split)
        float s[8][4] = {};
#pragma unroll
        for (int g=0; g<4; g++){
#pragma unroll
            for (int kk=0; kk<4; kk++){
                uint32_t bk[4], bkl[4];
                ldm_x4(bk,  st + krel + g*(16*AST*2) + kk*32);
                ldm_x4(bkl, st + RSZ + krel + g*(16*AST*2) + kk*32);
                mma_bf16(s[2*g],   qfh[kk], bk[0],  bk[1]);
                mma_bf16(s[2*g],   qfh[kk], bkl[0], bkl[1]);
                mma_bf16(s[2*g],   qfl[kk], bk[0],  bk[1]);
                mma_bf16(s[2*g+1], qfh[kk], bk[2],  bk[3]);
                mma_bf16(s[2*g+1], qfh[kk], bkl[2], bkl[3]);
                mma_bf16(s[2*g+1], qfl[kk], bk[2],  bk[3]);
            }
        }

        const int rl0 = wid*16 + gid;
        float mx0=-INFINITY, mx1=-INFINITY;
#pragma unroll
        for (int j=0; j<8; j++){
#pragma unroll
            for (int c=0; c<4; c++) s[j][c] *= 0.03125f;
            if (causal && kt == qt){
                int col = j*8 + 2*tq;
                if (col   > rl0)   s[j][0] = -1e9f;
                if (col+1 > rl0)   s[j][1] = -1e9f;
                if (col   > rl0+8) s[j][2] = -1e9f;
                if (col+1 > rl0+8) s[j][3] = -1e9f;
            }
            mx0 = fmaxf(mx0, fmaxf(s[j][0], s[j][1]));
            mx1 = fmaxf(mx1, fmaxf(s[j][2], s[j][3]));
        }
        mx0 = fmaxf(mx0, __shfl_xor_sync(~0u, mx0, 1));
        mx0 = fmaxf(mx0, __shfl_xor_sync(~0u, mx0, 2));
        mx1 = fmaxf(mx1, __shfl_xor_sync(~0u, mx1, 1));
        mx1 = fmaxf(mx1, __shfl_xor_sync(~0u, mx1, 2));
        float mn0 = fmaxf(m0, mx0), mn1 = fmaxf(m1, mx1);
        float f0 = __expf(m0 - mn0), f1 = __expf(m1 - mn1);
        m0 = mn0; m1 = mn1; l0 *= f0; l1 *= f1;
#pragma unroll
        for (int j=0; j<8; j++){
            s[j][0] = __expf(s[j][0]-m0); s[j][1] = __expf(s[j][1]-m0);
            s[j][2] = __expf(s[j][2]-m1); s[j][3] = __expf(s[j][3]-m1);
            l0 += s[j][0] + s[j][1];
            l1 += s[j][2] + s[j][3];
            acc[j][0]*=f0; acc[j][1]*=f0; acc[j][2]*=f1; acc[j][3]*=f1;
        }

        // O += P V
#pragma unroll
        for (int g=0; g<4; g++){
            float* t0 = s[2*g]; float* t1 = s[2*g+1];
            bf16 h00=bfh(t0[0]), h01=bfh(t0[1]), h02=bfh(t0[2]), h03=bfh(t0[3]);
            bf16 h10=bfh(t1[0]), h11=bfh(t1[1]), h12=bfh(t1[2]), h13=bfh(t1[3]);
            uint32_t aph[4] = { pack2(h00,h01), pack2(h02,h03), pack2(h10,h11), pack2(h12,h13) };
            uint32_t apl[4] = {
                pack2(bfh(t0[0]-bff(h00)), bfh(t0[1]-bff(h01))),
                pack2(bfh(t0[2]-bff(h02)), bfh(t0[3]-bff(h03))),
                pack2(bfh(t1[0]-bff(h10)), bfh(t1[1]-bff(h11))),
                pack2(bfh(t1[2]-bff(h12)), bfh(t1[3]-bff(h13))) };
#pragma unroll
            for (int jj=0; jj<4; jj++){
                uint32_t bv[4], bvl[4];
                ldm_x4t(bv,  st + 2*RSZ + vrel + g*(16*AST*2) + jj*32);
                ldm_x4t(bvl, st + 3*RSZ + vrel + g*(16*AST*2) + jj*32);
                mma_bf16(acc[2*jj],   aph, bv[0],  bv[1]);
                mma_bf16(acc[2*jj],   aph, bvl[0], bvl[1]);
                mma_bf16(acc[2*jj],   apl, bv[0],  bv[1]);
                mma_bf16(acc[2*jj+1], aph, bv[2],  bv[3]);
                mma_bf16(acc[2*jj+1], aph, bvl[2], bvl[3]);
                mma_bf16(acc[2*jj+1], apl, bv[2],  bv[3]);
            }
        }
    }

    l0 += __shfl_xor_sync(~0u, l0, 1); l0 += __shfl_xor_sync(~0u, l0, 2);
    l1 += __shfl_xor_sync(~0u, l1, 1); l1 += __shfl_xor_sync(~0u, l1, 2);
    float inv0 = 1.f/l0, inv1 = 1.f/l1;
    const size_t orow = qrow0 + wid*2;
#pragma unroll
    for (int j=0; j<8; j++){
        int col = gid*64 + j*8 + 2*tq;
        float o0 = acc[j][0]*inv0, o1 = acc[j][1]*inv0;
        float o2 = acc[j][2]*inv1, o3 = acc[j][3]*inv1;
        bf16 h0=bfh(o0), h1=bfh(o1), h2=bfh(o2), h3=bfh(o3);
        *(uint32_t*)(OH + orow*512 + col)     = pack2(h0,h1);
        *(uint32_t*)(OH + (orow+1)*512 + col) = pack2(h2,h3);
        *(uint32_t*)(OL + orow*512 + col)     = pack2(bfh(o0-bff(h0)), bfh(o1-bff(h1)));
        *(uint32_t*)(OL + (orow+1)*512 + col) = pack2(bfh(o2-bff(h2)), bfh(o3-bff(h3)));
    }
}

// ---------------- orchestration ----------------
extern "C" void kernel_launch(void* const* d_in, const int* in_sizes, int n_in,
                              void* d_out, int out_size)
{
    const float* memory   = (const float*)d_in[0];
    const float* target   = (const float*)d_in[1];
    const float* expand_w = (const float*)d_in[3];
    const float* expand_b = (const float*)d_in[4];
    const float* ln_w     = (const float*)d_in[5];
    const float* ln_b     = (const float*)d_in[6];
    const float* attn_w   = (const float*)d_in[7];
    const float* attn_b   = (const float*)d_in[8];
    const float* ff_w1    = (const float*)d_in[9];
    const float* ff_b1    = (const float*)d_in[10];
    const float* ff_w2    = (const float*)d_in[11];
    const float* ff_b2    = (const float*)d_in[12];
    float* out = (float*)d_out;

    float *t;
    bf16 *xh,*xl,*qkvh,*qkvl,*kvh,*kvl,*aoh,*aol,*memh,*meml,*ffh,*ffl,*inh,*inl;
    bf16 *whA,*wlA,*wh1,*wl1,*wh2,*wl2,*whe,*wle;
    cudaGetSymbolAddress((void**)&t,  g_t);
    cudaGetSymbolAddress((void**)&xh, g_xh);
    cudaGetSymbolAddress((void**)&xl, g_xl);
    cudaGetSymbolAddress((void**)&qkvh,g_qkvh);
    cudaGetSymbolAddress((void**)&qkvl,g_qkvl);
    cudaGetSymbolAddress((void**)&kvh,g_kvh);
    cudaGetSymbolAddress((void**)&kvl,g_kvl);
    cudaGetSymbolAddress((void**)&aoh,g_aoh);
    cudaGetSymbolAddress((void**)&aol,g_aol);
    cudaGetSymbolAddress((void**)&memh,g_memh);
    cudaGetSymbolAddress((void**)&meml,g_meml);
    cudaGetSymbolAddress((void**)&ffh,g_ffh);
    cudaGetSymbolAddress((void**)&ffl,g_ffl);
    cudaGetSymbolAddress((void**)&inh,g_inh);
    cudaGetSymbolAddress((void**)&inl,g_inl);
    cudaGetSymbolAddress((void**)&whA,g_wh_attn);
    cudaGetSymbolAddress((void**)&wlA,g_wl_attn);
    cudaGetSymbolAddress((void**)&wh1,g_wh_ff1);
    cudaGetSymbolAddress((void**)&wl1,g_wl_ff1);
    cudaGetSymbolAddress((void**)&wh2,g_wh_ff2);
    cudaGetSymbolAddress((void**)&wl2,g_wl_ff2);
    cudaGetSymbolAddress((void**)&whe,g_wh_exp);
    cudaGetSymbolAddress((void**)&wle,g_wl_exp);

    cudaFuncSetAttribute(tc_gemm,  cudaFuncAttributeMaxDynamicSharedMemorySize, GEMM_SMEM);
    cudaFuncSetAttribute(attn_mma, cudaFuncAttributeMaxDynamicSharedMemorySize, ATT_SMEM);

    tsplit_kernel<<<dim3(16,16,48), dim3(32,8)>>>(attn_w,   whA, wlA, 512, 512);
    tsplit_kernel<<<dim3(64,16,6),  dim3(32,8)>>>(ff_w1,    wh1, wl1, 512, 2048);
    tsplit_kernel<<<dim3(16,64,6),  dim3(32,8)>>>(ff_w2,    wh2, wl2, 2048, 512);
    tsplit_kernel<<<dim3(16,4,1),   dim3(32,8)>>>(expand_w, whe, wle, 128, 512);
    csplit_kernel<<<MROWS*128/256, 256>>>(memory, inh, inl, MROWS*128);

    auto G = [&](const bf16* AH, const bf16* AL, const bf16* WH, const bf16* WL,
                 const float* bi, const bf16* rH, const bf16* rL,
                 float* Cf, bf16* CH, bf16* CL, int K, int N, int act){
        tc_gemm<<<dim3(N/BN, MROWS/BM), 256, GEMM_SMEM>>>(AH, AL, WH, WL, bi, rH, rL, Cf, CH, CL, K, N, act);
    };
    const dim3 ga(8, 128);

    G(inh, inl, whe, wle, expand_b, nullptr, nullptr, nullptr, memh, meml, 128, 512, 1);

    const float* tin = target;
    for (int l=0; l<NLAYERS; l++){
        const size_t wo = (size_t)l*8*262144;
        const float* ab = attn_b + (size_t)l*8*DDIM;
        const float* lw = ln_w + (size_t)l*3*DDIM;
        const float* lb = ln_b + (size_t)l*3*DDIM;

        // self-attention (fused QKV)
        ln_kernel<<<MROWS/2,256>>>(tin, lw, lb, xh, xl);
        G(xh, xl, whA+wo, wlA+wo, ab, nullptr, nullptr, nullptr, qkvh, qkvl, 512, 1536, 0);
        attn_mma<<<ga,128,ATT_SMEM>>>(qkvh, qkvl, 1536, qkvh+512, qkvl+512, 1536,
                                      qkvh+1024, qkvl+1024, 1536, aoh, aol, 1);
        G(aoh, aol, whA+wo+3ull*262144, wlA+wo+3ull*262144, ab+3*DDIM, xh, xl, t, nullptr, nullptr, 512, 512, 0);

        // cross-attention (fused KV)
        ln_kernel<<<MROWS/2,256>>>(t, lw+DDIM, lb+DDIM, xh, xl);
        G(xh, xl, whA+wo+4ull*262144, wlA+wo+4ull*262144, ab+4*DDIM, nullptr, nullptr, nullptr, qkvh, qkvl, 512, 512, 0);
        G(memh, meml, whA+wo+5ull*262144, wlA+wo+5ull*262144, ab+5*DDIM, nullptr, nullptr, nullptr, kvh, kvl, 512, 1024, 0);
        attn_mma<<<ga,128,ATT_SMEM>>>(qkvh, qkvl, 512, kvh, kvl, 1024,
                                      kvh+512, kvl+512, 1024, aoh, aol, 0);
        G(aoh, aol, whA+wo+7ull*262144, wlA+wo+7ull*262144, ab+7*DDIM, xh, xl, t, nullptr, nullptr, 512, 512, 0);

        // feed-forward
        ln_kernel<<<MROWS/2,256>>>(t, lw+2*DDIM, lb+2*DDIM, xh, xl);
        G(xh, xl, wh1+(size_t)l*DDIM*FFF, wl1+(size_t)l*DDIM*FFF, ff_b1+(size_t)l*FFF,
          nullptr, nullptr, nullptr, ffh, ffl, 512, 2048, 1);
        float* dst = (l==NLAYERS-1) ? out : t;
        G(ffh, ffl, wh2+(size_t)l*FFF*DDIM, wl2+(size_t)l*FFF*DDIM, ff_b2+(size_t)l*DDIM,
          nullptr, nullptr, dst, nullptr, nullptr, 2048, 512, 2);
        tin = t;
    }
}

// round 16
// speedup vs baseline: 1.0128x; 1.0031x over previous
#include <cuda_runtime.h>
#include <cuda_bf16.h>
#include <cstdint>
#include <math.h>

#define BB 16
#define DDIM 512
#define FFF 2048
#define NLAYERS 6
#define MROWS (BB*512)

typedef __nv_bfloat16 bf16;
typedef __nv_bfloat162 bf162;

// ---------------- scratch ----------------
__device__ __align__(256) float g_t [MROWS*DDIM];
__device__ __align__(256) bf16 g_xh [MROWS*DDIM];
__device__ __align__(256) bf16 g_xl [MROWS*DDIM];
__device__ __align__(256) bf16 g_qkvh[MROWS*1536];
__device__ __align__(256) bf16 g_qkvl[MROWS*1536];
__device__ __align__(256) bf16 g_kvh [MROWS*1024];
__device__ __align__(256) bf16 g_kvl [MROWS*1024];
__device__ __align__(256) bf16 g_aoh[MROWS*DDIM];
__device__ __align__(256) bf16 g_aol[MROWS*DDIM];
__device__ __align__(256) bf16 g_memh[MROWS*DDIM];
__device__ __align__(256) bf16 g_meml[MROWS*DDIM];
__device__ __align__(256) bf16 g_ffh[MROWS*FFF];
__device__ __align__(256) bf16 g_ffl[MROWS*FFF];
__device__ __align__(256) bf16 g_inh[MROWS*128];
__device__ __align__(256) bf16 g_inl[MROWS*128];
__device__ __align__(256) bf16 g_wh_attn[48*512*512];
__device__ __align__(256) bf16 g_wl_attn[48*512*512];
__device__ __align__(256) bf16 g_wh_ff1 [6*2048*512];
__device__ __align__(256) bf16 g_wl_ff1 [6*2048*512];
__device__ __align__(256) bf16 g_wh_ff2 [6*512*2048];
__device__ __align__(256) bf16 g_wl_ff2 [6*512*2048];
__device__ __align__(256) bf16 g_wh_exp [512*128];
__device__ __align__(256) bf16 g_wl_exp [512*128];

// ---------------- helpers ----------------
__device__ __forceinline__ uint32_t smem_u32(const void* p){
    uint32_t a; asm("{ .reg .u64 t; cvta.to.shared.u64 t, %1; cvt.u32.u64 %0, t; }":"=r"(a):"l"(p)); return a;
}
__device__ __forceinline__ void ldm_x4(uint32_t* r, uint32_t addr){
    asm volatile("ldmatrix.sync.aligned.m8n8.x4.shared.b16 {%0,%1,%2,%3}, [%4];"
        : "=r"(r[0]),"=r"(r[1]),"=r"(r[2]),"=r"(r[3]) : "r"(addr));
}
__device__ __forceinline__ void ldm_x4t(uint32_t* r, uint32_t addr){
    asm volatile("ldmatrix.sync.aligned.m8n8.x4.trans.shared.b16 {%0,%1,%2,%3}, [%4];"
        : "=r"(r[0]),"=r"(r[1]),"=r"(r[2]),"=r"(r[3]) : "r"(addr));
}
__device__ __forceinline__ void cpa16(uint32_t dst, const void* src){
    asm volatile("cp.async.cg.shared.global [%0], [%1], 16;" :: "r"(dst), "l"(src));
}
__device__ __forceinline__ void mma_bf16(float* d, const uint32_t* a, uint32_t b0, uint32_t b1){
    asm volatile(
        "mma.sync.aligned.m16n8k16.row.col.f32.bf16.bf16.f32 "
        "{%0,%1,%2,%3}, {%4,%5,%6,%7}, {%8,%9}, {%0,%1,%2,%3};"
        : "+f"(d[0]), "+f"(d[1]), "+f"(d[2]), "+f"(d[3])
        : "r"(a[0]), "r"(a[1]), "r"(a[2]), "r"(a[3]), "r"(b0), "r"(b1));
}
__device__ __forceinline__ uint32_t pack2(bf16 a, bf16 b){ bf162 h; h.x=a; h.y=b; return *(uint32_t*)&h; }
__device__ __forceinline__ bf16 bfh(float v){ return __float2bfloat16_rn(v); }
__device__ __forceinline__ float bff(bf16 v){ return __bfloat162float(v); }

// ---------------- transpose + split weights ----------------
__global__ void tsplit_kernel(const float* __restrict__ W, bf16* __restrict__ Hi,
                              bf16* __restrict__ Lo, int K, int N)
{
    __shared__ float t[32][33];
    const float* Wm = W + (size_t)blockIdx.z*K*N;
    bf16* Hm = Hi + (size_t)blockIdx.z*K*N;
    bf16* Lm = Lo + (size_t)blockIdx.z*K*N;
    int n0=blockIdx.x*32, k0=blockIdx.y*32, x=threadIdx.x, y=threadIdx.y;
#pragma unroll
    for (int i=0;i<32;i+=8) t[y+i][x] = Wm[(size_t)(k0+y+i)*N + n0+x];
    __syncthreads();
#pragma unroll
    for (int i=0;i<32;i+=8){
        float v = t[x][y+i];
        bf16 h = bfh(v);
        Hm[(size_t)(n0+y+i)*K + k0+x] = h;
        Lm[(size_t)(n0+y+i)*K + k0+x] = bfh(v - bff(h));
    }
}
__global__ void csplit_kernel(const float* __restrict__ X, bf16* __restrict__ H,
                              bf16* __restrict__ L, int n)
{
    int i = blockIdx.x*blockDim.x + threadIdx.x;
    if (i < n){
        float v = X[i];
        bf16 h = bfh(v);
        H[i] = h; L[i] = bfh(v - bff(h));
    }
}

// ---------------- GEMM core (R10 proven) ----------------
#define BM 128
#define BN 128
#define BK 32
#define SROW 80
#define OPSZ (128*SROW)
#define STG (4*OPSZ)
#define GEMM_SMEM (2*STG)

struct GemmCtx {
    const bf16 *Ah, *Al, *Bh, *Bl;
    const float* bias;
    const bf16 *resH, *resL;
    float* Cf; bf16 *CH, *CL;
    int K, N, m0, n0, act;
};

__device__ __forceinline__ void gemm_core(const GemmCtx& g, char* sm)
{
    const uint32_t sbase = smem_u32(sm);
    const int tid = threadIdx.x, lane = tid&31, wid = tid>>5;
    const int gid = lane>>2, tq = lane&3;
    const int wm = wid&1, wn = wid>>1;
    const int K = g.K, N = g.N, m0 = g.m0, n0 = g.n0;
    const bf16* Ah = g.Ah; const bf16* Al = g.Al;
    const bf16* Bh = g.Bh; const bf16* Bl = g.Bl;
    const int KT = K/BK;

    const int lrow = tid>>2, lc = tid&3;
    auto LOAD = [&](int kt){
        uint32_t st = sbase + (kt&1)*STG;
#pragma unroll
        for (int i=0;i<2;i++){
            int row = lrow + i*64;
            uint32_t off = (uint32_t)row*SROW + lc*16;
            size_t go = (size_t)row*K + kt*BK + lc*8;
            cpa16(st+off, Ah+go);
            cpa16(st+OPSZ+off, Al+go);
            cpa16(st+2*OPSZ+off, Bh+go);
            cpa16(st+3*OPSZ+off, Bl+go);
        }
        asm volatile("cp.async.commit_group;" ::: "memory");
    };
    const uint32_t aoff = (uint32_t)((wm*64 + (lane&15))*SROW + ((lane>>4)*16));
    const uint32_t boff = (uint32_t)((wn*32 + ((lane>>4)*8) + (lane&7))*SROW + (((lane>>3)&1)*16));

    float acc[4][4][4] = {};
    LOAD(0);
    for (int kt=0; kt<KT; kt++){
        if (kt+1 < KT) LOAD(kt+1);
        if (kt+1 < KT) asm volatile("cp.async.wait_group 1;" ::: "memory");
        else           asm volatile("cp.async.wait_group 0;" ::: "memory");
        __syncthreads();
        const uint32_t st = sbase + (kt&1)*STG;
#pragma unroll
        for (int k16=0; k16<2; k16++){
            const uint32_t ko = k16*32;
            uint32_t ah[4][4], al[4][4];
#pragma unroll
            for (int i=0;i<4;i++){
                ldm_x4(ah[i], st + aoff + i*16*SROW + ko);
                ldm_x4(al[i], st + OPSZ + aoff + i*16*SROW + ko);
            }
#pragma unroll
            for (int jj=0; jj<2; jj++){
                uint32_t bh4[4], bl4[4];
                ldm_x4(bh4, st + 2*OPSZ + boff + jj*16*SROW + ko);
                ldm_x4(bl4, st + 3*OPSZ + boff + jj*16*SROW + ko);
#pragma unroll
                for (int jh=0; jh<2; jh++){
                    const int j = jj*2 + jh;
                    uint32_t b0 = bh4[2*jh], b1 = bh4[2*jh+1];
                    uint32_t c0 = bl4[2*jh], c1 = bl4[2*jh+1];
#pragma unroll
                    for (int i=0;i<4;i++){
                        mma_bf16(acc[i][j], ah[i], b0, b1);
                        mma_bf16(acc[i][j], ah[i], c0, c1);
                        mma_bf16(acc[i][j], al[i], b0, b1);
                    }
                }
            }
        }
        __syncthreads();
    }
#pragma unroll
    for (int i=0;i<4;i++){
        const int r0 = m0 + wm*64 + i*16 + gid;
#pragma unroll
        for (int j=0;j<4;j++){
            const int c = n0 + wn*32 + j*8 + 2*tq;
            float b0 = g.bias[c], b1 = g.bias[c+1];
            float v[4] = {acc[i][j][0]+b0, acc[i][j][1]+b1, acc[i][j][2]+b0, acc[i][j][3]+b1};
            if (g.resH){
                uint32_t rh0 = *(const uint32_t*)(g.resH + (size_t)r0*N + c);
                uint32_t rl0u = *(const uint32_t*)(g.resL + (size_t)r0*N + c);
                uint32_t rh1 = *(const uint32_t*)(g.resH + (size_t)(r0+8)*N + c);
                uint32_t rl1u = *(const uint32_t*)(g.resL + (size_t)(r0+8)*N + c);
                bf162 h0 = *(bf162*)&rh0, l0v = *(bf162*)&rl0u;
                bf162 h1 = *(bf162*)&rh1, l1v = *(bf162*)&rl1u;
                v[0] += bff(h0.x)+bff(l0v.x); v[1] += bff(h0.y)+bff(l0v.y);
                v[2] += bff(h1.x)+bff(l1v.x); v[3] += bff(h1.y)+bff(l1v.y);
            }
            if (g.act==1){
#pragma unroll
                for (int u=0;u<4;u++) v[u] = v[u]>0.f ? v[u] : 0.01f*v[u];
            } else if (g.act==2){
#pragma unroll
                for (int u=0;u<4;u++) v[u] = 2.f*(v[u]>0.f ? v[u] : 0.01f*v[u]);
            }
            if (g.Cf){
                *(float2*)(g.Cf + (size_t)r0*N + c)     = make_float2(v[0], v[1]);
                *(float2*)(g.Cf + (size_t)(r0+8)*N + c) = make_float2(v[2], v[3]);
            }
            if (g.CH){
                bf16 h0=bfh(v[0]), h1=bfh(v[1]), h2=bfh(v[2]), h3=bfh(v[3]);
                *(uint32_t*)(g.CH + (size_t)r0*N + c)     = pack2(h0,h1);
                *(uint32_t*)(g.CH + (size_t)(r0+8)*N + c) = pack2(h2,h3);
                *(uint32_t*)(g.CL + (size_t)r0*N + c) =
                    pack2(bfh(v[0]-bff(h0)), bfh(v[1]-bff(h1)));
                *(uint32_t*)(g.CL + (size_t)(r0+8)*N + c) =
                    pack2(bfh(v[2]-bff(h2)), bfh(v[3]-bff(h3)));
            }
        }
    }
}

__global__ __launch_bounds__(256, 2)
void tc_gemm(const bf16* __restrict__ AHg, const bf16* __restrict__ ALg,
             const bf16* __restrict__ WH, const bf16* __restrict__ WL,
             const float* __restrict__ bias,
             const bf16* __restrict__ resH, const bf16* __restrict__ resL,
             float* __restrict__ Cf, bf16* __restrict__ CH, bf16* __restrict__ CL,
             int K, int N, int act)
{
    extern __shared__ char sm[];
    GemmCtx g;
    g.m0 = blockIdx.y*BM; g.n0 = blockIdx.x*BN;
    g.Ah = AHg + (size_t)g.m0*K; g.Al = ALg + (size_t)g.m0*K;
    g.Bh = WH + (size_t)g.n0*K;  g.Bl = WL + (size_t)g.n0*K;
    g.bias = bias; g.resH = resH; g.resL = resL;
    g.Cf = Cf; g.CH = CH; g.CL = CL; g.K = K; g.N = N; g.act = act;
    gemm_core(g, sm);
}

// merged cross-attn Q (set0: N=512, 4 x-tiles) + KV (set1: N=1024, 8 x-tiles); K=512, act=0
__global__ __launch_bounds__(256, 2)
void tc_gemm2(const bf16* __restrict__ A0h, const bf16* __restrict__ A0l,
              const bf16* __restrict__ W0h, const bf16* __restrict__ W0l,
              const float* __restrict__ b0, bf16* __restrict__ C0h, bf16* __restrict__ C0l,
              const bf16* __restrict__ A1h, const bf16* __restrict__ A1l,
              const bf16* __restrict__ W1h, const bf16* __restrict__ W1l,
              const float* __restrict__ b1, bf16* __restrict__ C1h, bf16* __restrict__ C1l)
{
    extern __shared__ char sm[];
    GemmCtx g;
    const int K = 512;
    g.m0 = blockIdx.y*BM;
    g.K = K; g.act = 0; g.Cf = nullptr; g.resH = nullptr; g.resL = nullptr;
    if (blockIdx.x < 4){
        g.n0 = blockIdx.x*BN; g.N = 512;
        g.Ah = A0h + (size_t)g.m0*K; g.Al = A0l + (size_t)g.m0*K;
        g.Bh = W0h + (size_t)g.n0*K; g.Bl = W0l + (size_t)g.n0*K;
        g.bias = b0; g.CH = C0h; g.CL = C0l;
    } else {
        g.n0 = (blockIdx.x-4)*BN; g.N = 1024;
        g.Ah = A1h + (size_t)g.m0*K; g.Al = A1l + (size_t)g.m0*K;
        g.Bh = W1h + (size_t)g.n0*K; g.Bl = W1l + (size_t)g.n0*K;
        g.bias = b1; g.CH = C1h; g.CL = C1l;
    }
    gemm_core(g, sm);
}

// ---------------- LayerNorm: 512 threads, 4 rows/block ----------------
__global__ void ln_kernel(const float* __restrict__ X, const float* __restrict__ w,
                          const float* __restrict__ b,
                          bf16* __restrict__ YH, bf16* __restrict__ YL)
{
    const int tid = threadIdx.x;
    const int sub = tid >> 7;              // 0..3
    const int t   = tid & 127;
    const int row = blockIdx.x*4 + sub;
    float4 v = ((const float4*)(X + (size_t)row*512))[t];
    float s = v.x+v.y+v.z+v.w, ss = v.x*v.x+v.y*v.y+v.z*v.z+v.w*v.w;
#pragma unroll
    for (int o=16;o>0;o>>=1){ s+=__shfl_xor_sync(~0u,s,o); ss+=__shfl_xor_sync(~0u,ss,o); }
    __shared__ float rs[4][4], rss[4][4];
    int wd=(t>>5), ln=t&31;
    if (ln==0){ rs[sub][wd]=s; rss[sub][wd]=ss; }
    __syncthreads();
    s=rs[sub][0]+rs[sub][1]+rs[sub][2]+rs[sub][3];
    ss=rss[sub][0]+rss[sub][1]+rss[sub][2]+rss[sub][3];
    float mean=s*(1.f/512.f), var=ss*(1.f/512.f)-mean*mean, inv=rsqrtf(var+1e-5f);
    float4 wv=((const float4*)w)[t], bv=((const float4*)b)[t], y;
    y.x=(v.x-mean)*inv*wv.x+bv.x; y.y=(v.y-mean)*inv*wv.y+bv.y;
    y.z=(v.z-mean)*inv*wv.z+bv.z; y.w=(v.w-mean)*inv*wv.w+bv.w;
    bf16 h0=bfh(y.x), h1=bfh(y.y), h2=bfh(y.z), h3=bfh(y.w);
    uint32_t* HH = (uint32_t*)(YH + (size_t)row*512);
    uint32_t* LL = (uint32_t*)(YL + (size_t)row*512);
    HH[t*2]   = pack2(h0,h1);
    HH[t*2+1] = pack2(h2,h3);
    LL[t*2]   = pack2(bfh(y.x-bff(h0)), bfh(y.y-bff(h1)));
    LL[t*2+1] = pack2(bfh(y.z-bff(h2)), bfh(y.w-bff(h3)));
}

// ---------------- attention: cp.async double-buffered K/V (R13 proven) ------
#define AST 72
#define RSZ (64*AST*2)
#define ATT_SMEM (8*RSZ)

__global__ __launch_bounds__(128)
void attn_mma(const bf16* __restrict__ Qh, const bf16* __restrict__ Ql, int qs,
              const bf16* __restrict__ Kh, const bf16* __restrict__ Kl, int ks,
              const bf16* __restrict__ Vh, const bf16* __restrict__ Vl, int vs,
              bf16* __restrict__ OH, bf16* __restrict__ OL, int causal)
{
    extern __shared__ char smc[];
    const uint32_t sb = smem_u32(smc);
    const int qt = causal ? (int)(gridDim.x - 1 - blockIdx.x) : (int)blockIdx.x;
    const int bh = blockIdx.y;
    const int b = bh >> 3, h = bh & 7;
    const int tid = threadIdx.x, lane = tid & 31, wid = tid >> 5;
    const int gid = lane >> 2, tq = lane & 3;
    const size_t qrow0 = (size_t)b*512 + h*64 + qt*8;
    const size_t krowb = (size_t)b*512 + h*64;
    const int ktmax = causal ? qt : 7;

    auto LOADKV = [&](int kt){
        const uint32_t st = sb + (kt&1)*(4*RSZ);
        const size_t krow = krowb + kt*8;
        for (int i = tid; i < 512; i += 128){
            int r = i >> 3, cc = (i & 7) * 8;
            size_t gk = (krow + (r>>3))*ks + (r&7)*64 + cc;
            size_t gv = (krow + (r>>3))*vs + (r&7)*64 + cc;
            uint32_t off = (uint32_t)(r*AST + cc)*2;
            cpa16(st + off,         Kh + gk);
            cpa16(st + RSZ + off,   Kl + gk);
            cpa16(st + 2*RSZ + off, Vh + gv);
            cpa16(st + 3*RSZ + off, Vl + gv);
        }
        asm volatile("cp.async.commit_group;" ::: "memory");
    };

    for (int i = tid; i < 512; i += 128){
        int r = i >> 3, cc = (i & 7) * 8;
        size_t g = (qrow0 + (r>>3))*qs + (r&7)*64 + cc;
        uint32_t off = (uint32_t)(r*AST + cc)*2;
        cpa16(sb + 4*RSZ + off, Qh + g);
        cpa16(sb + 5*RSZ + off, Ql + g);
    }
    asm volatile("cp.async.commit_group;" ::: "memory");
    LOADKV(0);
    asm volatile("cp.async.wait_group 0;" ::: "memory");
    __syncthreads();

    const uint32_t qlane = (uint32_t)(((wid*16 + (lane&15))*AST + (lane>>4)*8)*2);
    const uint32_t krel  = (uint32_t)(((((lane>>4)*8) + (lane&7))*AST + ((lane>>3)&1)*8)*2);
    const uint32_t vrel  = (uint32_t)(((((lane&7) + ((lane>>3)&1)*8)*AST) + (lane>>4)*8)*2);

    uint32_t qfh[4][4], qfl[4][4];
#pragma unroll
    for (int g=0; g<4; g++){
        ldm_x4(qfh[g], sb + 4*RSZ + qlane + g*32);
        ldm_x4(qfl[g], sb + 5*RSZ + qlane + g*32);
    }
    __syncthreads();

    float m0=-INFINITY, m1=-INFINITY, l0=0.f, l1=0.f;
    float acc[8][4] = {};

    for (int kt=0; kt<=ktmax; kt++){
        if (kt > 0){
            asm volatile("cp.async.wait_group 0;" ::: "memory");
            __syncthreads();
        }
        if (kt+1 <= ktmax) LOADKV(kt+1);
        const uint32_t st = sb + (kt&1)*(4*RSZ);

        float s[8][4] = {};
#pragma unroll
        for (int g=0; g<4; g++){
#pragma unroll
            for (int kk=0; kk<4; kk++){
                uint32_t bk[4], bkl[4];
                ldm_x4(bk,  st + krel + g*(16*AST*2) + kk*32);
                ldm_x4(bkl, st + RSZ + krel + g*(16*AST*2) + kk*32);
                mma_bf16(s[2*g],   qfh[kk], bk[0],  bk[1]);
                mma_bf16(s[2*g],   qfh[kk], bkl[0], bkl[1]);
                mma_bf16(s[2*g],   qfl[kk], bk[0],  bk[1]);
                mma_bf16(s[2*g+1], qfh[kk], bk[2],  bk[3]);
                mma_bf16(s[2*g+1], qfh[kk], bkl[2], bkl[3]);
                mma_bf16(s[2*g+1], qfl[kk], bk[2],  bk[3]);
            }
        }

        const int rl0 = wid*16 + gid;
        float mx0=-INFINITY, mx1=-INFINITY;
#pragma unroll
        for (int j=0; j<8; j++){
#pragma unroll
            for (int c=0; c<4; c++) s[j][c] *= 0.03125f;
            if (causal && kt == qt){
                int col = j*8 + 2*tq;
                if (col   > rl0)   s[j][0] = -1e9f;
                if (col+1 > rl0)   s[j][1] = -1e9f;
                if (col   > rl0+8) s[j][2] = -1e9f;
                if (col+1 > rl0+8) s[j][3] = -1e9f;
            }
            mx0 = fmaxf(mx0, fmaxf(s[j][0], s[j][1]));
            mx1 = fmaxf(mx1, fmaxf(s[j][2], s[j][3]));
        }
        mx0 = fmaxf(mx0, __shfl_xor_sync(~0u, mx0, 1));
        mx0 = fmaxf(mx0, __shfl_xor_sync(~0u, mx0, 2));
        mx1 = fmaxf(mx1, __shfl_xor_sync(~0u, mx1, 1));
        mx1 = fmaxf(mx1, __shfl_xor_sync(~0u, mx1, 2));
        float mn0 = fmaxf(m0, mx0), mn1 = fmaxf(m1, mx1);
        float f0 = __expf(m0 - mn0), f1 = __expf(m1 - mn1);
        m0 = mn0; m1 = mn1; l0 *= f0; l1 *= f1;
#pragma unroll
        for (int j=0; j<8; j++){
            s[j][0] = __expf(s[j][0]-m0); s[j][1] = __expf(s[j][1]-m0);
            s[j][2] = __expf(s[j][2]-m1); s[j][3] = __expf(s[j][3]-m1);
            l0 += s[j][0] + s[j][1];
            l1 += s[j][2] + s[j][3];
            acc[j][0]*=f0; acc[j][1]*=f0; acc[j][2]*=f1; acc[j][3]*=f1;
        }

#pragma unroll
        for (int g=0; g<4; g++){
            float* t0 = s[2*g]; float* t1 = s[2*g+1];
            bf16 h00=bfh(t0[0]), h01=bfh(t0[1]), h02=bfh(t0[2]), h03=bfh(t0[3]);
            bf16 h10=bfh(t1[0]), h11=bfh(t1[1]), h12=bfh(t1[2]), h13=bfh(t1[3]);
            uint32_t aph[4] = { pack2(h00,h01), pack2(h02,h03), pack2(h10,h11), pack2(h12,h13) };
            uint32_t apl[4] = {
                pack2(bfh(t0[0]-bff(h00)), bfh(t0[1]-bff(h01))),
                pack2(bfh(t0[2]-bff(h02)), bfh(t0[3]-bff(h03))),
                pack2(bfh(t1[0]-bff(h10)), bfh(t1[1]-bff(h11))),
                pack2(bfh(t1[2]-bff(h12)), bfh(t1[3]-bff(h13))) };
#pragma unroll
            for (int jj=0; jj<4; jj++){
                uint32_t bv[4], bvl[4];
                ldm_x4t(bv,  st + 2*RSZ + vrel + g*(16*AST*2) + jj*32);
                ldm_x4t(bvl, st + 3*RSZ + vrel + g*(16*AST*2) + jj*32);
                mma_bf16(acc[2*jj],   aph, bv[0],  bv[1]);
                mma_bf16(acc[2*jj],   aph, bvl[0], bvl[1]);
                mma_bf16(acc[2*jj],   apl, bv[0],  bv[1]);
                mma_bf16(acc[2*jj+1], aph, bv[2],  bv[3]);
                mma_bf16(acc[2*jj+1], aph, bvl[2], bvl[3]);
                mma_bf16(acc[2*jj+1], apl, bv[2],  bv[3]);
            }
        }
    }

    l0 += __shfl_xor_sync(~0u, l0, 1); l0 += __shfl_xor_sync(~0u, l0, 2);
    l1 += __shfl_xor_sync(~0u, l1, 1); l1 += __shfl_xor_sync(~0u, l1, 2);
    float inv0 = 1.f/l0, inv1 = 1.f/l1;
    const size_t orow = qrow0 + wid*2;
#pragma unroll
    for (int j=0; j<8; j++){
        int col = gid*64 + j*8 + 2*tq;
        float o0 = acc[j][0]*inv0, o1 = acc[j][1]*inv0;
        float o2 = acc[j][2]*inv1, o3 = acc[j][3]*inv1;
        bf16 h0=bfh(o0), h1=bfh(o1), h2=bfh(o2), h3=bfh(o3);
        *(uint32_t*)(OH + orow*512 + col)     = pack2(h0,h1);
        *(uint32_t*)(OH + (orow+1)*512 + col) = pack2(h2,h3);
        *(uint32_t*)(OL + orow*512 + col)     = pack2(bfh(o0-bff(h0)), bfh(o1-bff(h1)));
        *(uint32_t*)(OL + (orow+1)*512 + col) = pack2(bfh(o2-bff(h2)), bfh(o3-bff(h3)));
    }
}

// ---------------- orchestration ----------------
extern "C" void kernel_launch(void* const* d_in, const int* in_sizes, int n_in,
                              void* d_out, int out_size)
{
    const float* memory   = (const float*)d_in[0];
    const float* target   = (const float*)d_in[1];
    const float* expand_w = (const float*)d_in[3];
    const float* expand_b = (const float*)d_in[4];
    const float* ln_w     = (const float*)d_in[5];
    const float* ln_b     = (const float*)d_in[6];
    const float* attn_w   = (const float*)d_in[7];
    const float* attn_b   = (const float*)d_in[8];
    const float* ff_w1    = (const float*)d_in[9];
    const float* ff_b1    = (const float*)d_in[10];
    const float* ff_w2    = (const float*)d_in[11];
    const float* ff_b2    = (const float*)d_in[12];
    float* out = (float*)d_out;

    float *t;
    bf16 *xh,*xl,*qkvh,*qkvl,*kvh,*kvl,*aoh,*aol,*memh,*meml,*ffh,*ffl,*inh,*inl;
    bf16 *whA,*wlA,*wh1,*wl1,*wh2,*wl2,*whe,*wle;
    cudaGetSymbolAddress((void**)&t,  g_t);
    cudaGetSymbolAddress((void**)&xh, g_xh);
    cudaGetSymbolAddress((void**)&xl, g_xl);
    cudaGetSymbolAddress((void**)&qkvh,g_qkvh);
    cudaGetSymbolAddress((void**)&qkvl,g_qkvl);
    cudaGetSymbolAddress((void**)&kvh,g_kvh);
    cudaGetSymbolAddress((void**)&kvl,g_kvl);
    cudaGetSymbolAddress((void**)&aoh,g_aoh);
    cudaGetSymbolAddress((void**)&aol,g_aol);
    cudaGetSymbolAddress((void**)&memh,g_memh);
    cudaGetSymbolAddress((void**)&meml,g_meml);
    cudaGetSymbolAddress((void**)&ffh,g_ffh);
    cudaGetSymbolAddress((void**)&ffl,g_ffl);
    cudaGetSymbolAddress((void**)&inh,g_inh);
    cudaGetSymbolAddress((void**)&inl,g_inl);
    cudaGetSymbolAddress((void**)&whA,g_wh_attn);
    cudaGetSymbolAddress((void**)&wlA,g_wl_attn);
    cudaGetSymbolAddress((void**)&wh1,g_wh_ff1);
    cudaGetSymbolAddress((void**)&wl1,g_wl_ff1);
    cudaGetSymbolAddress((void**)&wh2,g_wh_ff2);
    cudaGetSymbolAddress((void**)&wl2,g_wl_ff2);
    cudaGetSymbolAddress((void**)&whe,g_wh_exp);
    cudaGetSymbolAddress((void**)&wle,g_wl_exp);

    cudaFuncSetAttribute(tc_gemm,  cudaFuncAttributeMaxDynamicSharedMemorySize, GEMM_SMEM);
    cudaFuncSetAttribute(tc_gemm2, cudaFuncAttributeMaxDynamicSharedMemorySize, GEMM_SMEM);
    cudaFuncSetAttribute(attn_mma, cudaFuncAttributeMaxDynamicSharedMemorySize, ATT_SMEM);

    tsplit_kernel<<<dim3(16,16,48), dim3(32,8)>>>(attn_w,   whA, wlA, 512, 512);
    tsplit_kernel<<<dim3(64,16,6),  dim3(32,8)>>>(ff_w1,    wh1, wl1, 512, 2048);
    tsplit_kernel<<<dim3(16,64,6),  dim3(32,8)>>>(ff_w2,    wh2, wl2, 2048, 512);
    tsplit_kernel<<<dim3(16,4,1),   dim3(32,8)>>>(expand_w, whe, wle, 128, 512);
    csplit_kernel<<<MROWS*128/256, 256>>>(memory, inh, inl, MROWS*128);

    auto G = [&](const bf16* AH, const bf16* AL, const bf16* WH, const bf16* WL,
                 const float* bi, const bf16* rH, const bf16* rL,
                 float* Cf, bf16* CH, bf16* CL, int K, int N, int act){
        tc_gemm<<<dim3(N/BN, MROWS/BM), 256, GEMM_SMEM>>>(AH, AL, WH, WL, bi, rH, rL, Cf, CH, CL, K, N, act);
    };
    const dim3 ga(8, 128);

    G(inh, inl, whe, wle, expand_b, nullptr, nullptr, nullptr, memh, meml, 128, 512, 1);

    const float* tin = target;
    for (int l=0; l<NLAYERS; l++){
        const size_t wo = (size_t)l*8*262144;
        const float* ab = attn_b + (size_t)l*8*DDIM;
        const float* lw = ln_w + (size_t)l*3*DDIM;
        const float* lb = ln_b + (size_t)l*3*DDIM;

        // self-attention (fused QKV)
        ln_kernel<<<MROWS/4,512>>>(tin, lw, lb, xh, xl);
        G(xh, xl, whA+wo, wlA+wo, ab, nullptr, nullptr, nullptr, qkvh, qkvl, 512, 1536, 0);
        attn_mma<<<ga,128,ATT_SMEM>>>(qkvh, qkvl, 1536, qkvh+512, qkvl+512, 1536,
                                      qkvh+1024, qkvl+1024, 1536, aoh, aol, 1);
        G(aoh, aol, whA+wo+3ull*262144, wlA+wo+3ull*262144, ab+3*DDIM, xh, xl, t, nullptr, nullptr, 512, 512, 0);

        // cross-attention: merged Q + KV projection (one launch)
        ln_kernel<<<MROWS/4,512>>>(t, lw+DDIM, lb+DDIM, xh, xl);
        tc_gemm2<<<dim3(12, MROWS/BM), 256, GEMM_SMEM>>>(
            xh, xl, whA+wo+4ull*262144, wlA+wo+4ull*262144, ab+4*DDIM, qkvh, qkvl,
            memh, meml, whA+wo+5ull*262144, wlA+wo+5ull*262144, ab+5*DDIM, kvh, kvl);
        attn_mma<<<ga,128,ATT_SMEM>>>(qkvh, qkvl, 512, kvh, kvl, 1024,
                                      kvh+512, kvl+512, 1024, aoh, aol, 0);
        G(aoh, aol, whA+wo+7ull*262144, wlA+wo+7ull*262144, ab+7*DDIM, xh, xl, t, nullptr, nullptr, 512, 512, 0);

        // feed-forward
        ln_kernel<<<MROWS/4,512>>>(t, lw+2*DDIM, lb+2*DDIM, xh, xl);
        G(xh, xl, wh1+(size_t)l*DDIM*FFF, wl1+(size_t)l*DDIM*FFF, ff_b1+(size_t)l*FFF,
          nullptr, nullptr, nullptr, ffh, ffl, 512, 2048, 1);
        float* dst = (l==NLAYERS-1) ? out : t;
        G(ffh, ffl, wh2+(size_t)l*FFF*DDIM, wl2+(size_t)l*FFF*DDIM, ff_b2+(size_t)l*DDIM,
          nullptr, nullptr, dst, nullptr, nullptr, 2048, 512, 2);
        tin = t;
    }
}

// round 17
// speedup vs baseline: 1.0139x; 1.0011x over previous
#include <cuda_runtime.h>
#include <cuda_bf16.h>
#include <cstdint>
#include <math.h>

#define BB 16
#define DDIM 512
#define FFF 2048
#define NLAYERS 6
#define MROWS (BB*512)

typedef __nv_bfloat16 bf16;
typedef __nv_bfloat162 bf162;

// ---------------- scratch ----------------
__device__ __align__(256) float g_t [MROWS*DDIM];
__device__ __align__(256) bf16 g_xh [MROWS*DDIM];
__device__ __align__(256) bf16 g_xl [MROWS*DDIM];
__device__ __align__(256) bf16 g_qkvh[MROWS*1536];
__device__ __align__(256) bf16 g_qkvl[MROWS*1536];
__device__ __align__(256) bf16 g_kvh [MROWS*1024];
__device__ __align__(256) bf16 g_kvl [MROWS*1024];
__device__ __align__(256) bf16 g_aoh[MROWS*DDIM];
__device__ __align__(256) bf16 g_aol[MROWS*DDIM];
__device__ __align__(256) bf16 g_memh[MROWS*DDIM];
__device__ __align__(256) bf16 g_meml[MROWS*DDIM];
__device__ __align__(256) bf16 g_ffh[MROWS*FFF];
__device__ __align__(256) bf16 g_ffl[MROWS*FFF];
__device__ __align__(256) bf16 g_inh[MROWS*128];
__device__ __align__(256) bf16 g_inl[MROWS*128];
__device__ __align__(256) bf16 g_wh_attn[48*512*512];
__device__ __align__(256) bf16 g_wl_attn[48*512*512];
__device__ __align__(256) bf16 g_wh_ff1 [6*2048*512];
__device__ __align__(256) bf16 g_wl_ff1 [6*2048*512];
__device__ __align__(256) bf16 g_wh_ff2 [6*512*2048];
__device__ __align__(256) bf16 g_wl_ff2 [6*512*2048];
__device__ __align__(256) bf16 g_wh_exp [512*128];
__device__ __align__(256) bf16 g_wl_exp [512*128];

// ---------------- helpers ----------------
__device__ __forceinline__ uint32_t smem_u32(const void* p){
    uint32_t a; asm("{ .reg .u64 t; cvta.to.shared.u64 t, %1; cvt.u32.u64 %0, t; }":"=r"(a):"l"(p)); return a;
}
__device__ __forceinline__ void ldm_x4(uint32_t* r, uint32_t addr){
    asm volatile("ldmatrix.sync.aligned.m8n8.x4.shared.b16 {%0,%1,%2,%3}, [%4];"
        : "=r"(r[0]),"=r"(r[1]),"=r"(r[2]),"=r"(r[3]) : "r"(addr));
}
__device__ __forceinline__ void ldm_x4t(uint32_t* r, uint32_t addr){
    asm volatile("ldmatrix.sync.aligned.m8n8.x4.trans.shared.b16 {%0,%1,%2,%3}, [%4];"
        : "=r"(r[0]),"=r"(r[1]),"=r"(r[2]),"=r"(r[3]) : "r"(addr));
}
__device__ __forceinline__ void cpa16(uint32_t dst, const void* src){
    asm volatile("cp.async.cg.shared.global [%0], [%1], 16;" :: "r"(dst), "l"(src));
}
__device__ __forceinline__ void mma_bf16(float* d, const uint32_t* a, uint32_t b0, uint32_t b1){
    asm volatile(
        "mma.sync.aligned.m16n8k16.row.col.f32.bf16.bf16.f32 "
        "{%0,%1,%2,%3}, {%4,%5,%6,%7}, {%8,%9}, {%0,%1,%2,%3};"
        : "+f"(d[0]), "+f"(d[1]), "+f"(d[2]), "+f"(d[3])
        : "r"(a[0]), "r"(a[1]), "r"(a[2]), "r"(a[3]), "r"(b0), "r"(b1));
}
__device__ __forceinline__ uint32_t pack2(bf16 a, bf16 b){ bf162 h; h.x=a; h.y=b; return *(uint32_t*)&h; }
__device__ __forceinline__ bf16 bfh(float v){ return __float2bfloat16_rn(v); }
__device__ __forceinline__ float bff(bf16 v){ return __bfloat162float(v); }

// ---------------- unified prepass: all weight splits + memory csplit --------
// regions (block ranges): [0,12288) attn, [12288,18432) ff1, [18432,24576) ff2,
// [24576,24640) exp, [24640,28736) memory csplit.
__device__ __forceinline__ void tsplit_tile(const float* __restrict__ W,
                                            bf16* __restrict__ Hi, bf16* __restrict__ Lo,
                                            int K, int N, int z, int gx, int gy,
                                            float (*t)[33], int tid)
{
    const float* Wm = W + (size_t)z*K*N;
    bf16* Hm = Hi + (size_t)z*K*N;
    bf16* Lm = Lo + (size_t)z*K*N;
    int n0 = gx*32, k0 = gy*32;
    int x = tid & 31, y = tid >> 5;     // 32 x 8
#pragma unroll
    for (int i=0;i<32;i+=8) t[y+i][x] = Wm[(size_t)(k0+y+i)*N + n0+x];
    __syncthreads();
#pragma unroll
    for (int i=0;i<32;i+=8){
        float v = t[x][y+i];
        bf16 h = bfh(v);
        Hm[(size_t)(n0+y+i)*K + k0+x] = h;
        Lm[(size_t)(n0+y+i)*K + k0+x] = bfh(v - bff(h));
    }
}

__global__ void prep_kernel(const float* __restrict__ attn_w, const float* __restrict__ ff_w1,
                            const float* __restrict__ ff_w2, const float* __restrict__ expand_w,
                            const float* __restrict__ memory)
{
    __shared__ float t[32][33];
    const int bidx = blockIdx.x, tid = threadIdx.x;
    if (bidx < 12288){
        int z = bidx >> 8, rem = bidx & 255;
        tsplit_tile(attn_w, g_wh_attn, g_wl_attn, 512, 512, z, rem & 15, rem >> 4, t, tid);
    } else if (bidx < 18432){
        int b = bidx - 12288;
        int z = b >> 10, rem = b & 1023;
        tsplit_tile(ff_w1, g_wh_ff1, g_wl_ff1, 512, 2048, z, rem & 63, rem >> 6, t, tid);
    } else if (bidx < 24576){
        int b = bidx - 18432;
        int z = b >> 10, rem = b & 1023;
        tsplit_tile(ff_w2, g_wh_ff2, g_wl_ff2, 2048, 512, z, rem & 15, rem >> 4, t, tid);
    } else if (bidx < 24640){
        int b = bidx - 24576;
        tsplit_tile(expand_w, g_wh_exp, g_wl_exp, 128, 512, 0, b & 15, b >> 4, t, tid);
    } else {
        int i = (bidx - 24640)*256 + tid;   // exactly covers MROWS*128 = 1048576
        float v = memory[i];
        bf16 h = bfh(v);
        g_inh[i] = h;
        g_inl[i] = bfh(v - bff(h));
    }
}

// ---------------- GEMM core (R10 proven) ----------------
#define BM 128
#define BN 128
#define BK 32
#define SROW 80
#define OPSZ (128*SROW)
#define STG (4*OPSZ)
#define GEMM_SMEM (2*STG)

struct GemmCtx {
    const bf16 *Ah, *Al, *Bh, *Bl;
    const float* bias;
    const bf16 *resH, *resL;
    float* Cf; bf16 *CH, *CL;
    int K, N, m0, n0, act;
};

__device__ __forceinline__ void gemm_core(const GemmCtx& g, char* sm)
{
    const uint32_t sbase = smem_u32(sm);
    const int tid = threadIdx.x, lane = tid&31, wid = tid>>5;
    const int gid = lane>>2, tq = lane&3;
    const int wm = wid&1, wn = wid>>1;
    const int K = g.K, N = g.N, m0 = g.m0, n0 = g.n0;
    const bf16* Ah = g.Ah; const bf16* Al = g.Al;
    const bf16* Bh = g.Bh; const bf16* Bl = g.Bl;
    const int KT = K/BK;

    const int lrow = tid>>2, lc = tid&3;
    auto LOAD = [&](int kt){
        uint32_t st = sbase + (kt&1)*STG;
#pragma unroll
        for (int i=0;i<2;i++){
            int row = lrow + i*64;
            uint32_t off = (uint32_t)row*SROW + lc*16;
            size_t go = (size_t)row*K + kt*BK + lc*8;
            cpa16(st+off, Ah+go);
            cpa16(st+OPSZ+off, Al+go);
            cpa16(st+2*OPSZ+off, Bh+go);
            cpa16(st+3*OPSZ+off, Bl+go);
        }
        asm volatile("cp.async.commit_group;" ::: "memory");
    };
    const uint32_t aoff = (uint32_t)((wm*64 + (lane&15))*SROW + ((lane>>4)*16));
    const uint32_t boff = (uint32_t)((wn*32 + ((lane>>4)*8) + (lane&7))*SROW + (((lane>>3)&1)*16));

    float acc[4][4][4] = {};
    LOAD(0);
    for (int kt=0; kt<KT; kt++){
        if (kt+1 < KT) LOAD(kt+1);
        if (kt+1 < KT) asm volatile("cp.async.wait_group 1;" ::: "memory");
        else           asm volatile("cp.async.wait_group 0;" ::: "memory");
        __syncthreads();
        const uint32_t st = sbase + (kt&1)*STG;
#pragma unroll
        for (int k16=0; k16<2; k16++){
            const uint32_t ko = k16*32;
            uint32_t ah[4][4], al[4][4];
#pragma unroll
            for (int i=0;i<4;i++){
                ldm_x4(ah[i], st + aoff + i*16*SROW + ko);
                ldm_x4(al[i], st + OPSZ + aoff + i*16*SROW + ko);
            }
#pragma unroll
            for (int jj=0; jj<2; jj++){
                uint32_t bh4[4], bl4[4];
                ldm_x4(bh4, st + 2*OPSZ + boff + jj*16*SROW + ko);
                ldm_x4(bl4, st + 3*OPSZ + boff + jj*16*SROW + ko);
#pragma unroll
                for (int jh=0; jh<2; jh++){
                    const int j = jj*2 + jh;
                    uint32_t b0 = bh4[2*jh], b1 = bh4[2*jh+1];
                    uint32_t c0 = bl4[2*jh], c1 = bl4[2*jh+1];
#pragma unroll
                    for (int i=0;i<4;i++){
                        mma_bf16(acc[i][j], ah[i], b0, b1);
                        mma_bf16(acc[i][j], ah[i], c0, c1);
                        mma_bf16(acc[i][j], al[i], b0, b1);
                    }
                }
            }
        }
        __syncthreads();
    }
#pragma unroll
    for (int i=0;i<4;i++){
        const int r0 = m0 + wm*64 + i*16 + gid;
#pragma unroll
        for (int j=0;j<4;j++){
            const int c = n0 + wn*32 + j*8 + 2*tq;
            float b0 = g.bias[c], b1 = g.bias[c+1];
            float v[4] = {acc[i][j][0]+b0, acc[i][j][1]+b1, acc[i][j][2]+b0, acc[i][j][3]+b1};
            if (g.resH){
                uint32_t rh0 = *(const uint32_t*)(g.resH + (size_t)r0*N + c);
                uint32_t rl0u = *(const uint32_t*)(g.resL + (size_t)r0*N + c);
                uint32_t rh1 = *(const uint32_t*)(g.resH + (size_t)(r0+8)*N + c);
                uint32_t rl1u = *(const uint32_t*)(g.resL + (size_t)(r0+8)*N + c);
                bf162 h0 = *(bf162*)&rh0, l0v = *(bf162*)&rl0u;
                bf162 h1 = *(bf162*)&rh1, l1v = *(bf162*)&rl1u;
                v[0] += bff(h0.x)+bff(l0v.x); v[1] += bff(h0.y)+bff(l0v.y);
                v[2] += bff(h1.x)+bff(l1v.x); v[3] += bff(h1.y)+bff(l1v.y);
            }
            if (g.act==1){
#pragma unroll
                for (int u=0;u<4;u++) v[u] = v[u]>0.f ? v[u] : 0.01f*v[u];
            } else if (g.act==2){
#pragma unroll
                for (int u=0;u<4;u++) v[u] = 2.f*(v[u]>0.f ? v[u] : 0.01f*v[u]);
            }
            if (g.Cf){
                *(float2*)(g.Cf + (size_t)r0*N + c)     = make_float2(v[0], v[1]);
                *(float2*)(g.Cf + (size_t)(r0+8)*N + c) = make_float2(v[2], v[3]);
            }
            if (g.CH){
                bf16 h0=bfh(v[0]), h1=bfh(v[1]), h2=bfh(v[2]), h3=bfh(v[3]);
                *(uint32_t*)(g.CH + (size_t)r0*N + c)     = pack2(h0,h1);
                *(uint32_t*)(g.CH + (size_t)(r0+8)*N + c) = pack2(h2,h3);
                *(uint32_t*)(g.CL + (size_t)r0*N + c) =
                    pack2(bfh(v[0]-bff(h0)), bfh(v[1]-bff(h1)));
                *(uint32_t*)(g.CL + (size_t)(r0+8)*N + c) =
                    pack2(bfh(v[2]-bff(h2)), bfh(v[3]-bff(h3)));
            }
        }
    }
}

__global__ __launch_bounds__(256, 2)
void tc_gemm(const bf16* __restrict__ AHg, const bf16* __restrict__ ALg,
             const bf16* __restrict__ WH, const bf16* __restrict__ WL,
             const float* __restrict__ bias,
             const bf16* __restrict__ resH, const bf16* __restrict__ resL,
             float* __restrict__ Cf, bf16* __restrict__ CH, bf16* __restrict__ CL,
             int K, int N, int act)
{
    extern __shared__ char sm[];
    GemmCtx g;
    g.m0 = blockIdx.y*BM; g.n0 = blockIdx.x*BN;
    g.Ah = AHg + (size_t)g.m0*K; g.Al = ALg + (size_t)g.m0*K;
    g.Bh = WH + (size_t)g.n0*K;  g.Bl = WL + (size_t)g.n0*K;
    g.bias = bias; g.resH = resH; g.resL = resL;
    g.Cf = Cf; g.CH = CH; g.CL = CL; g.K = K; g.N = N; g.act = act;
    gemm_core(g, sm);
}

__global__ __launch_bounds__(256, 2)
void tc_gemm2(const bf16* __restrict__ A0h, const bf16* __restrict__ A0l,
              const bf16* __restrict__ W0h, const bf16* __restrict__ W0l,
              const float* __restrict__ b0, bf16* __restrict__ C0h, bf16* __restrict__ C0l,
              const bf16* __restrict__ A1h, const bf16* __restrict__ A1l,
              const bf16* __restrict__ W1h, const bf16* __restrict__ W1l,
              const float* __restrict__ b1, bf16* __restrict__ C1h, bf16* __restrict__ C1l)
{
    extern __shared__ char sm[];
    GemmCtx g;
    const int K = 512;
    g.m0 = blockIdx.y*BM;
    g.K = K; g.act = 0; g.Cf = nullptr; g.resH = nullptr; g.resL = nullptr;
    if (blockIdx.x < 4){
        g.n0 = blockIdx.x*BN; g.N = 512;
        g.Ah = A0h + (size_t)g.m0*K; g.Al = A0l + (size_t)g.m0*K;
        g.Bh = W0h + (size_t)g.n0*K; g.Bl = W0l + (size_t)g.n0*K;
        g.bias = b0; g.CH = C0h; g.CL = C0l;
    } else {
        g.n0 = (blockIdx.x-4)*BN; g.N = 1024;
        g.Ah = A1h + (size_t)g.m0*K; g.Al = A1l + (size_t)g.m0*K;
        g.Bh = W1h + (size_t)g.n0*K; g.Bl = W1l + (size_t)g.n0*K;
        g.bias = b1; g.CH = C1h; g.CL = C1l;
    }
    gemm_core(g, sm);
}

// ---------------- LayerNorm: 512 threads, 4 rows/block ----------------
__global__ void ln_kernel(const float* __restrict__ X, const float* __restrict__ w,
                          const float* __restrict__ b,
                          bf16* __restrict__ YH, bf16* __restrict__ YL)
{
    const int tid = threadIdx.x;
    const int sub = tid >> 7;
    const int t   = tid & 127;
    const int row = blockIdx.x*4 + sub;
    float4 v = ((const float4*)(X + (size_t)row*512))[t];
    float s = v.x+v.y+v.z+v.w, ss = v.x*v.x+v.y*v.y+v.z*v.z+v.w*v.w;
#pragma unroll
    for (int o=16;o>0;o>>=1){ s+=__shfl_xor_sync(~0u,s,o); ss+=__shfl_xor_sync(~0u,ss,o); }
    __shared__ float rs[4][4], rss[4][4];
    int wd=(t>>5), ln=t&31;
    if (ln==0){ rs[sub][wd]=s; rss[sub][wd]=ss; }
    __syncthreads();
    s=rs[sub][0]+rs[sub][1]+rs[sub][2]+rs[sub][3];
    ss=rss[sub][0]+rss[sub][1]+rss[sub][2]+rss[sub][3];
    float mean=s*(1.f/512.f), var=ss*(1.f/512.f)-mean*mean, inv=rsqrtf(var+1e-5f);
    float4 wv=((const float4*)w)[t], bv=((const float4*)b)[t], y;
    y.x=(v.x-mean)*inv*wv.x+bv.x; y.y=(v.y-mean)*inv*wv.y+bv.y;
    y.z=(v.z-mean)*inv*wv.z+bv.z; y.w=(v.w-mean)*inv*wv.w+bv.w;
    bf16 h0=bfh(y.x), h1=bfh(y.y), h2=bfh(y.z), h3=bfh(y.w);
    uint32_t* HH = (uint32_t*)(YH + (size_t)row*512);
    uint32_t* LL = (uint32_t*)(YL + (size_t)row*512);
    HH[t*2]   = pack2(h0,h1);
    HH[t*2+1] = pack2(h2,h3);
    LL[t*2]   = pack2(bfh(y.x-bff(h0)), bfh(y.y-bff(h1)));
    LL[t*2+1] = pack2(bfh(y.z-bff(h2)), bfh(y.w-bff(h3)));
}

// ---------------- attention: cp.async double-buffered K/V (R13 proven) ------
#define AST 72
#define RSZ (64*AST*2)
#define ATT_SMEM (8*RSZ)

__global__ __launch_bounds__(128)
void attn_mma(const bf16* __restrict__ Qh, const bf16* __restrict__ Ql, int qs,
              const bf16* __restrict__ Kh, const bf16* __restrict__ Kl, int ks,
              const bf16* __restrict__ Vh, const bf16* __restrict__ Vl, int vs,
              bf16* __restrict__ OH, bf16* __restrict__ OL, int causal)
{
    extern __shared__ char smc[];
    const uint32_t sb = smem_u32(smc);
    const int qt = causal ? (int)(gridDim.x - 1 - blockIdx.x) : (int)blockIdx.x;
    const int bh = blockIdx.y;
    const int b = bh >> 3, h = bh & 7;
    const int tid = threadIdx.x, lane = tid & 31, wid = tid >> 5;
    const int gid = lane >> 2, tq = lane & 3;
    const size_t qrow0 = (size_t)b*512 + h*64 + qt*8;
    const size_t krowb = (size_t)b*512 + h*64;
    const int ktmax = causal ? qt : 7;

    auto LOADKV = [&](int kt){
        const uint32_t st = sb + (kt&1)*(4*RSZ);
        const size_t krow = krowb + kt*8;
        for (int i = tid; i < 512; i += 128){
            int r = i >> 3, cc = (i & 7) * 8;
            size_t gk = (krow + (r>>3))*ks + (r&7)*64 + cc;
            size_t gv = (krow + (r>>3))*vs + (r&7)*64 + cc;
            uint32_t off = (uint32_t)(r*AST + cc)*2;
            cpa16(st + off,         Kh + gk);
            cpa16(st + RSZ + off,   Kl + gk);
            cpa16(st + 2*RSZ + off, Vh + gv);
            cpa16(st + 3*RSZ + off, Vl + gv);
        }
        asm volatile("cp.async.commit_group;" ::: "memory");
    };

    for (int i = tid; i < 512; i += 128){
        int r = i >> 3, cc = (i & 7) * 8;
        size_t g = (qrow0 + (r>>3))*qs + (r&7)*64 + cc;
        uint32_t off = (uint32_t)(r*AST + cc)*2;
        cpa16(sb + 4*RSZ + off, Qh + g);
        cpa16(sb + 5*RSZ + off, Ql + g);
    }
    asm volatile("cp.async.commit_group;" ::: "memory");
    LOADKV(0);
    asm volatile("cp.async.wait_group 0;" ::: "memory");
    __syncthreads();

    const uint32_t qlane = (uint32_t)(((wid*16 + (lane&15))*AST + (lane>>4)*8)*2);
    const uint32_t krel  = (uint32_t)(((((lane>>4)*8) + (lane&7))*AST + ((lane>>3)&1)*8)*2);
    const uint32_t vrel  = (uint32_t)(((((lane&7) + ((lane>>3)&1)*8)*AST) + (lane>>4)*8)*2);

    uint32_t qfh[4][4], qfl[4][4];
#pragma unroll
    for (int g=0; g<4; g++){
        ldm_x4(qfh[g], sb + 4*RSZ + qlane + g*32);
        ldm_x4(qfl[g], sb + 5*RSZ + qlane + g*32);
    }
    __syncthreads();

    float m0=-INFINITY, m1=-INFINITY, l0=0.f, l1=0.f;
    float acc[8][4] = {};

    for (int kt=0; kt<=ktmax; kt++){
        if (kt > 0){
            asm volatile("cp.async.wait_group 0;" ::: "memory");
            __syncthreads();
        }
        if (kt+1 <= ktmax) LOADKV(kt+1);
        const uint32_t st = sb + (kt&1)*(4*RSZ);

        float s[8][4] = {};
#pragma unroll
        for (int g=0; g<4; g++){
#pragma unroll
            for (int kk=0; kk<4; kk++){
                uint32_t bk[4], bkl[4];
                ldm_x4(bk,  st + krel + g*(16*AST*2) + kk*32);
                ldm_x4(bkl, st + RSZ + krel + g*(16*AST*2) + kk*32);
                mma_bf16(s[2*g],   qfh[kk], bk[0],  bk[1]);
                mma_bf16(s[2*g],   qfh[kk], bkl[0], bkl[1]);
                mma_bf16(s[2*g],   qfl[kk], bk[0],  bk[1]);
                mma_bf16(s[2*g+1], qfh[kk], bk[2],  bk[3]);
                mma_bf16(s[2*g+1], qfh[kk], bkl[2], bkl[3]);
                mma_bf16(s[2*g+1], qfl[kk], bk[2],  bk[3]);
            }
        }

        const int rl0 = wid*16 + gid;
        float mx0=-INFINITY, mx1=-INFINITY;
#pragma unroll
        for (int j=0; j<8; j++){
#pragma unroll
            for (int c=0; c<4; c++) s[j][c] *= 0.03125f;
            if (causal && kt == qt){
                int col = j*8 + 2*tq;
                if (col   > rl0)   s[j][0] = -1e9f;
                if (col+1 > rl0)   s[j][1] = -1e9f;
                if (col   > rl0+8) s[j][2] = -1e9f;
                if (col+1 > rl0+8) s[j][3] = -1e9f;
            }
            mx0 = fmaxf(mx0, fmaxf(s[j][0], s[j][1]));
            mx1 = fmaxf(mx1, fmaxf(s[j][2], s[j][3]));
        }
        mx0 = fmaxf(mx0, __shfl_xor_sync(~0u, mx0, 1));
        mx0 = fmaxf(mx0, __shfl_xor_sync(~0u, mx0, 2));
        mx1 = fmaxf(mx1, __shfl_xor_sync(~0u, mx1, 1));
        mx1 = fmaxf(mx1, __shfl_xor_sync(~0u, mx1, 2));
        float mn0 = fmaxf(m0, mx0), mn1 = fmaxf(m1, mx1);
        float f0 = __expf(m0 - mn0), f1 = __expf(m1 - mn1);
        m0 = mn0; m1 = mn1; l0 *= f0; l1 *= f1;
#pragma unroll
        for (int j=0; j<8; j++){
            s[j][0] = __expf(s[j][0]-m0); s[j][1] = __expf(s[j][1]-m0);
            s[j][2] = __expf(s[j][2]-m1); s[j][3] = __expf(s[j][3]-m1);
            l0 += s[j][0] + s[j][1];
            l1 += s[j][2] + s[j][3];
            acc[j][0]*=f0; acc[j][1]*=f0; acc[j][2]*=f1; acc[j][3]*=f1;
        }

#pragma unroll
        for (int g=0; g<4; g++){
            float* t0 = s[2*g]; float* t1 = s[2*g+1];
            bf16 h00=bfh(t0[0]), h01=bfh(t0[1]), h02=bfh(t0[2]), h03=bfh(t0[3]);
            bf16 h10=bfh(t1[0]), h11=bfh(t1[1]), h12=bfh(t1[2]), h13=bfh(t1[3]);
            uint32_t aph[4] = { pack2(h00,h01), pack2(h02,h03), pack2(h10,h11), pack2(h12,h13) };
            uint32_t apl[4] = {
                pack2(bfh(t0[0]-bff(h00)), bfh(t0[1]-bff(h01))),
                pack2(bfh(t0[2]-bff(h02)), bfh(t0[3]-bff(h03))),
                pack2(bfh(t1[0]-bff(h10)), bfh(t1[1]-bff(h11))),
                pack2(bfh(t1[2]-bff(h12)), bfh(t1[3]-bff(h13))) };
#pragma unroll
            for (int jj=0; jj<4; jj++){
                uint32_t bv[4], bvl[4];
                ldm_x4t(bv,  st + 2*RSZ + vrel + g*(16*AST*2) + jj*32);
                ldm_x4t(bvl, st + 3*RSZ + vrel + g*(16*AST*2) + jj*32);
                mma_bf16(acc[2*jj],   aph, bv[0],  bv[1]);
                mma_bf16(acc[2*jj],   aph, bvl[0], bvl[1]);
                mma_bf16(acc[2*jj],   apl, bv[0],  bv[1]);
                mma_bf16(acc[2*jj+1], aph, bv[2],  bv[3]);
                mma_bf16(acc[2*jj+1], aph, bvl[2], bvl[3]);
                mma_bf16(acc[2*jj+1], apl, bv[2],  bv[3]);
            }
        }
    }

    l0 += __shfl_xor_sync(~0u, l0, 1); l0 += __shfl_xor_sync(~0u, l0, 2);
    l1 += __shfl_xor_sync(~0u, l1, 1); l1 += __shfl_xor_sync(~0u, l1, 2);
    float inv0 = 1.f/l0, inv1 = 1.f/l1;
    const size_t orow = qrow0 + wid*2;
#pragma unroll
    for (int j=0; j<8; j++){
        int col = gid*64 + j*8 + 2*tq;
        float o0 = acc[j][0]*inv0, o1 = acc[j][1]*inv0;
        float o2 = acc[j][2]*inv1, o3 = acc[j][3]*inv1;
        bf16 h0=bfh(o0), h1=bfh(o1), h2=bfh(o2), h3=bfh(o3);
        *(uint32_t*)(OH + orow*512 + col)     = pack2(h0,h1);
        *(uint32_t*)(OH + (orow+1)*512 + col) = pack2(h2,h3);
        *(uint32_t*)(OL + orow*512 + col)     = pack2(bfh(o0-bff(h0)), bfh(o1-bff(h1)));
        *(uint32_t*)(OL + (orow+1)*512 + col) = pack2(bfh(o2-bff(h2)), bfh(o3-bff(h3)));
    }
}

// ---------------- orchestration ----------------
extern "C" void kernel_launch(void* const* d_in, const int* in_sizes, int n_in,
                              void* d_out, int out_size)
{
    const float* memory   = (const float*)d_in[0];
    const float* target   = (const float*)d_in[1];
    const float* expand_w = (const float*)d_in[3];
    const float* expand_b = (const float*)d_in[4];
    const float* ln_w     = (const float*)d_in[5];
    const float* ln_b     = (const float*)d_in[6];
    const float* attn_w   = (const float*)d_in[7];
    const float* attn_b   = (const float*)d_in[8];
    const float* ff_w1    = (const float*)d_in[9];
    const float* ff_b1    = (const float*)d_in[10];
    const float* ff_w2    = (const float*)d_in[11];
    const float* ff_b2    = (const float*)d_in[12];
    float* out = (float*)d_out;

    float *t;
    bf16 *xh,*xl,*qkvh,*qkvl,*kvh,*kvl,*aoh,*aol,*memh,*meml,*ffh,*ffl,*inh,*inl;
    bf16 *whA,*wlA,*wh1,*wl1,*wh2,*wl2,*whe,*wle;
    cudaGetSymbolAddress((void**)&t,  g_t);
    cudaGetSymbolAddress((void**)&xh, g_xh);
    cudaGetSymbolAddress((void**)&xl, g_xl);
    cudaGetSymbolAddress((void**)&qkvh,g_qkvh);
    cudaGetSymbolAddress((void**)&qkvl,g_qkvl);
    cudaGetSymbolAddress((void**)&kvh,g_kvh);
    cudaGetSymbolAddress((void**)&kvl,g_kvl);
    cudaGetSymbolAddress((void**)&aoh,g_aoh);
    cudaGetSymbolAddress((void**)&aol,g_aol);
    cudaGetSymbolAddress((void**)&memh,g_memh);
    cudaGetSymbolAddress((void**)&meml,g_meml);
    cudaGetSymbolAddress((void**)&ffh,g_ffh);
    cudaGetSymbolAddress((void**)&ffl,g_ffl);
    cudaGetSymbolAddress((void**)&inh,g_inh);
    cudaGetSymbolAddress((void**)&inl,g_inl);
    cudaGetSymbolAddress((void**)&whA,g_wh_attn);
    cudaGetSymbolAddress((void**)&wlA,g_wl_attn);
    cudaGetSymbolAddress((void**)&wh1,g_wh_ff1);
    cudaGetSymbolAddress((void**)&wl1,g_wl_ff1);
    cudaGetSymbolAddress((void**)&wh2,g_wh_ff2);
    cudaGetSymbolAddress((void**)&wl2,g_wl_ff2);
    cudaGetSymbolAddress((void**)&whe,g_wh_exp);
    cudaGetSymbolAddress((void**)&wle,g_wl_exp);

    cudaFuncSetAttribute(tc_gemm,  cudaFuncAttributeMaxDynamicSharedMemorySize, GEMM_SMEM);
    cudaFuncSetAttribute(tc_gemm2, cudaFuncAttributeMaxDynamicSharedMemorySize, GEMM_SMEM);
    cudaFuncSetAttribute(attn_mma, cudaFuncAttributeMaxDynamicSharedMemorySize, ATT_SMEM);

    // unified prepass: all weight splits + memory csplit in one launch
    prep_kernel<<<28736, 256>>>(attn_w, ff_w1, ff_w2, expand_w, memory);

    auto G = [&](const bf16* AH, const bf16* AL, const bf16* WH, const bf16* WL,
                 const float* bi, const bf16* rH, const bf16* rL,
                 float* Cf, bf16* CH, bf16* CL, int K, int N, int act){
        tc_gemm<<<dim3(N/BN, MROWS/BM), 256, GEMM_SMEM>>>(AH, AL, WH, WL, bi, rH, rL, Cf, CH, CL, K, N, act);
    };
    const dim3 ga(8, 128);

    G(inh, inl, whe, wle, expand_b, nullptr, nullptr, nullptr, memh, meml, 128, 512, 1);

    const float* tin = target;
    for (int l=0; l<NLAYERS; l++){
        const size_t wo = (size_t)l*8*262144;
        const float* ab = attn_b + (size_t)l*8*DDIM;
        const float* lw = ln_w + (size_t)l*3*DDIM;
        const float* lb = ln_b + (size_t)l*3*DDIM;

        // self-attention (fused QKV)
        ln_kernel<<<MROWS/4,512>>>(tin, lw, lb, xh, xl);
        G(xh, xl, whA+wo, wlA+wo, ab, nullptr, nullptr, nullptr, qkvh, qkvl, 512, 1536, 0);
        attn_mma<<<ga,128,ATT_SMEM>>>(qkvh, qkvl, 1536, qkvh+512, qkvl+512, 1536,
                                      qkvh+1024, qkvl+1024, 1536, aoh, aol, 1);
        G(aoh, aol, whA+wo+3ull*262144, wlA+wo+3ull*262144, ab+3*DDIM, xh, xl, t, nullptr, nullptr, 512, 512, 0);

        // cross-attention: merged Q + KV projection (one launch)
        ln_kernel<<<MROWS/4,512>>>(t, lw+DDIM, lb+DDIM, xh, xl);
        tc_gemm2<<<dim3(12, MROWS/BM), 256, GEMM_SMEM>>>(
            xh, xl, whA+wo+4ull*262144, wlA+wo+4ull*262144, ab+4*DDIM, qkvh, qkvl,
            memh, meml, whA+wo+5ull*262144, wlA+wo+5ull*262144, ab+5*DDIM, kvh, kvl);
        attn_mma<<<ga,128,ATT_SMEM>>>(qkvh, qkvl, 512, kvh, kvl, 1024,
                                      kvh+512, kvl+512, 1024, aoh, aol, 0);
        G(aoh, aol, whA+wo+7ull*262144, wlA+wo+7ull*262144, ab+7*DDIM, xh, xl, t, nullptr, nullptr, 512, 512, 0);

        // feed-forward
        ln_kernel<<<MROWS/4,512>>>(t, lw+2*DDIM, lb+2*DDIM, xh, xl);
        G(xh, xl, wh1+(size_t)l*DDIM*FFF, wl1+(size_t)l*DDIM*FFF, ff_b1+(size_t)l*FFF,
          nullptr, nullptr, nullptr, ffh, ffl, 512, 2048, 1);
        float* dst = (l==NLAYERS-1) ? out : t;
        G(ffh, ffl, wh2+(size_t)l*FFF*DDIM, wl2+(size_t)l*FFF*DDIM, ff_b2+(size_t)l*DDIM,
          nullptr, nullptr, dst, nullptr, nullptr, 2048, 512, 2);
        tin = t;
    }
}